// round 11
// baseline (speedup 1.0000x reference)
#include <cuda_runtime.h>
#include <cuda_bf16.h>

// ---------------------------------------------------------------------------
// SparseConvNet: masked 3D conv pipeline + trilinear sampling, sm_103a.
//
// Exactness argument for sparsity: every layer output is y = relu(conv(x)*s+b)*mask,
// and every layer input is already masked. So outputs at mask==0 are exactly 0 and
// never need computing; conv at masked voxels reads neighbors from dense zero-padded
// buffers (zeros where unmasked). We therefore:
//   * keep zero-initialized padded channels-last __device__ scratch buffers,
//   * write ONLY masked voxels (pad + unmasked voxels stay 0 forever -> deterministic),
//   * iterate over compacted active-voxel lists built per launch.
// ---------------------------------------------------------------------------

static constexpr int L0 = 130;               // padded full-res line (128 + 2)
static constexpr int L1 = 66;                // padded half-res line (64 + 2)
static constexpr int NFULL = 128 * 128 * 128;
static constexpr int NHALF = 64 * 64 * 64;

// Scratch (zero-initialized at module load; pad & unmasked voxels never written)
__device__ __align__(16) float g_PX[L0 * L0 * L0 * 4];    // masked input, 4ch (3 real + 1 zero pad)
__device__ __align__(16) float g_P0[L0 * L0 * L0 * 16];   // after conv0a
__device__ __align__(16) float g_P1[L0 * L0 * L0 * 16];   // after conv0b
__device__ __align__(16) float g_Q2[L1 * L1 * L1 * 32];   // after convd0
__device__ __align__(16) float g_Q3[L1 * L1 * L1 * 32];   // after conv1a
__device__ __align__(16) float g_Q4[L1 * L1 * L1 * 32];   // after conv1b
__device__ unsigned g_list0[NFULL];
__device__ unsigned g_list1[NHALF];
__device__ int g_n0;
__device__ int g_n1;
// Repacked weights: [tap][cin_padded][cout], contiguous float4 along cout
__device__ __align__(16) float g_WR0A[27 * 4 * 16];
__device__ __align__(16) float g_WR0B[27 * 16 * 16];
__device__ __align__(16) float g_WRD0[27 * 16 * 32];
__device__ __align__(16) float g_WR1A[27 * 32 * 32];
__device__ __align__(16) float g_WR1B[27 * 32 * 32];

// ---------------------------------------------------------------------------
__global__ void k_reset() {
    if (threadIdx.x == 0) { g_n0 = 0; g_n1 = 0; }
}

// Repack weights from OIDHW (o, i, kz, ky, kx) to [tap][ci_padded][co].
template <int CINR, int CINP, int COUT>
__global__ void k_repack(const float* __restrict__ w, float* __restrict__ dst) {
    int i = blockIdx.x * blockDim.x + threadIdx.x;
    if (i >= 27 * CINP * COUT) return;
    int co = i % COUT;
    int r = i / COUT;
    int ci = r % CINP;
    int t = r / CINP;
    dst[i] = (ci < CINR) ? w[(co * CINR + ci) * 27 + t] : 0.0f;
}

// Build masked padded input (channels-last, 4ch) + active list at full res.
__global__ void k_prep(const float* __restrict__ xf, const int* __restrict__ mask) {
    int v = blockIdx.x * blockDim.x + threadIdx.x;
    if (v >= NFULL) return;
    if (mask[v] == 0) return;
    int xx = v & 127, yy = (v >> 7) & 127, zz = v >> 14;
    int vp = ((zz + 1) * L0 + (yy + 1)) * L0 + (xx + 1);
    float4 val;
    val.x = xf[v];
    val.y = xf[NFULL + v];
    val.z = xf[2 * NFULL + v];
    val.w = 0.0f;
    reinterpret_cast<float4*>(g_PX)[vp] = val;
    int pos = atomicAdd(&g_n0, 1);
    g_list0[pos] = (unsigned)((zz << 14) | (yy << 7) | xx);
}

// m1 = maxpool3 stride2 pad1 of mask; build half-res active list.
__global__ void k_m1(const int* __restrict__ mask) {
    int v = blockIdx.x * blockDim.x + threadIdx.x;
    if (v >= NHALF) return;
    int xx = v & 63, yy = (v >> 6) & 63, zz = v >> 12;
    int any = 0;
    for (int dz = 0; dz < 3; dz++) {
        int iz = 2 * zz - 1 + dz;
        if (iz < 0 || iz > 127) continue;
        for (int dy = 0; dy < 3; dy++) {
            int iy = 2 * yy - 1 + dy;
            if (iy < 0 || iy > 127) continue;
            for (int dx = 0; dx < 3; dx++) {
                int ix = 2 * xx - 1 + dx;
                if (ix < 0 || ix > 127) continue;
                any |= mask[(iz * 128 + iy) * 128 + ix];
            }
        }
    }
    if (any) {
        int pos = atomicAdd(&g_n1, 1);
        g_list1[pos] = (unsigned)((zz << 12) | (yy << 6) | xx);
    }
}

// ---------------------------------------------------------------------------
// Gather conv: each thread computes VPT active voxels x all COUT channels.
// Weights in shared (broadcast LDS.128: 8 FFMA per LDS.128), inputs LDG.128.
// LIN: padded input line, S: input coordinate stride (2 for downsample conv),
// LOUT: padded output line, B: bits per coord in packed list entry.
// ---------------------------------------------------------------------------
template <int CIN, int COUT, int VPT, int LIN, int S, int LOUT, int B>
__global__ void __launch_bounds__(256)
conv_gather(const float4* __restrict__ in4, float4* __restrict__ out4,
            const float4* __restrict__ wrep4,
            const float* __restrict__ scale, const float* __restrict__ shift,
            const unsigned* __restrict__ list, const int* __restrict__ pcount) {
    constexpr int C4 = CIN / 4;
    constexpr int O4 = COUT / 4;
    constexpr int WN4 = 27 * CIN * O4;

    extern __shared__ float4 smem4[];
    float4* w4s = smem4;
    float* s_sc = reinterpret_cast<float*>(smem4 + WN4);
    float* s_sh = s_sc + COUT;

    const int n = *pcount;
    const int base = blockIdx.x * (256 * VPT);
    if (base >= n) return;

    for (int i = threadIdx.x; i < WN4; i += 256) w4s[i] = wrep4[i];
    if (threadIdx.x < COUT) {
        s_sc[threadIdx.x] = scale[threadIdx.x];
        s_sh[threadIdx.x] = shift[threadIdx.x];
    }
    __syncthreads();

    int vin[VPT], vout[VPT];
    bool valid[VPT];
#pragma unroll
    for (int k = 0; k < VPT; k++) {
        int idx = base + k * 256 + (int)threadIdx.x;
        valid[k] = idx < n;
        unsigned p = list[valid[k] ? idx : base];  // base < n guaranteed
        int xx = (int)(p & ((1u << B) - 1));
        int yy = (int)((p >> B) & ((1u << B) - 1));
        int zz = (int)(p >> (2 * B));
        vin[k] = ((zz * S) * LIN + yy * S) * LIN + xx * S;  // padded coord of logical (z-1,y-1,x-1)
        vout[k] = ((zz + 1) * LOUT + (yy + 1)) * LOUT + (xx + 1);
    }

    float acc[VPT][COUT];
#pragma unroll
    for (int k = 0; k < VPT; k++)
#pragma unroll
        for (int c = 0; c < COUT; c++) acc[k][c] = 0.0f;

#pragma unroll 1
    for (int dz = 0; dz < 3; dz++) {
#pragma unroll 1
        for (int dy = 0; dy < 3; dy++) {
#pragma unroll 1
            for (int dx = 0; dx < 3; dx++) {
                const int t = (dz * 3 + dy) * 3 + dx;
                const int off = (dz * LIN + dy) * LIN + dx;
                const float4* wt = w4s + t * (CIN * O4);
                const float4* pin[VPT];
#pragma unroll
                for (int k = 0; k < VPT; k++) pin[k] = in4 + (size_t)(vin[k] + off) * C4;
#pragma unroll
                for (int c4 = 0; c4 < C4; c4++) {
                    float4 iv[VPT];
#pragma unroll
                    for (int k = 0; k < VPT; k++) iv[k] = __ldg(pin[k] + c4);
#pragma unroll
                    for (int j = 0; j < 4; j++) {
                        const float4* wrow = wt + (c4 * 4 + j) * O4;
                        float a[VPT];
#pragma unroll
                        for (int k = 0; k < VPT; k++)
                            a[k] = (j == 0) ? iv[k].x : (j == 1) ? iv[k].y : (j == 2) ? iv[k].z : iv[k].w;
#pragma unroll
                        for (int o4 = 0; o4 < O4; o4++) {
                            float4 w = wrow[o4];
#pragma unroll
                            for (int k = 0; k < VPT; k++) {
                                acc[k][4 * o4 + 0] = fmaf(a[k], w.x, acc[k][4 * o4 + 0]);
                                acc[k][4 * o4 + 1] = fmaf(a[k], w.y, acc[k][4 * o4 + 1]);
                                acc[k][4 * o4 + 2] = fmaf(a[k], w.z, acc[k][4 * o4 + 2]);
                                acc[k][4 * o4 + 3] = fmaf(a[k], w.w, acc[k][4 * o4 + 3]);
                            }
                        }
                    }
                }
            }
        }
    }

#pragma unroll
    for (int k = 0; k < VPT; k++) {
        if (!valid[k]) continue;
        float4* po = out4 + (size_t)vout[k] * O4;
#pragma unroll
        for (int o4 = 0; o4 < O4; o4++) {
            float4 r;
            r.x = fmaxf(fmaf(acc[k][4 * o4 + 0], s_sc[4 * o4 + 0], s_sh[4 * o4 + 0]), 0.0f);
            r.y = fmaxf(fmaf(acc[k][4 * o4 + 1], s_sc[4 * o4 + 1], s_sh[4 * o4 + 1]), 0.0f);
            r.z = fmaxf(fmaf(acc[k][4 * o4 + 2], s_sc[4 * o4 + 2], s_sh[4 * o4 + 2]), 0.0f);
            r.w = fmaxf(fmaf(acc[k][4 * o4 + 3], s_sc[4 * o4 + 3], s_sh[4 * o4 + 3]), 0.0f);
            po[o4] = r;
        }
    }
}

// ---------------------------------------------------------------------------
// Trilinear sampling of Q4 (66-padded, 32ch channels-last) at 65536 points.
// coords in [-1, 1): all 8 corners are in-bounds; clamps are no-op safety.
// ---------------------------------------------------------------------------
__global__ void k_sample(const float4* __restrict__ Q, const float* __restrict__ coords,
                         float4* __restrict__ out, int npts) {
    int p = blockIdx.x * blockDim.x + threadIdx.x;
    if (p >= npts) return;
    float fx = (coords[3 * p + 0] + 1.0f) * 0.5f * 63.0f;
    float fy = (coords[3 * p + 1] + 1.0f) * 0.5f * 63.0f;
    float fz = (coords[3 * p + 2] + 1.0f) * 0.5f * 63.0f;
    int ix = (int)floorf(fx); ix = max(0, min(ix, 62));
    int iy = (int)floorf(fy); iy = max(0, min(iy, 62));
    int iz = (int)floorf(fz); iz = max(0, min(iz, 62));
    float tx = fx - (float)ix;
    float ty = fy - (float)iy;
    float tz = fz - (float)iz;

    float4 acc[8];
#pragma unroll
    for (int o = 0; o < 8; o++) acc[o] = make_float4(0.f, 0.f, 0.f, 0.f);

#pragma unroll
    for (int dz = 0; dz < 2; dz++) {
#pragma unroll
        for (int dy = 0; dy < 2; dy++) {
#pragma unroll
            for (int dx = 0; dx < 2; dx++) {
                float w = (dx ? tx : 1.0f - tx) * (dy ? ty : 1.0f - ty) * (dz ? tz : 1.0f - tz);
                int vp = ((iz + dz + 1) * L1 + (iy + dy + 1)) * L1 + (ix + dx + 1);
                const float4* q = Q + (size_t)vp * 8;
#pragma unroll
                for (int o = 0; o < 8; o++) {
                    float4 v = __ldg(q + o);
                    acc[o].x = fmaf(w, v.x, acc[o].x);
                    acc[o].y = fmaf(w, v.y, acc[o].y);
                    acc[o].z = fmaf(w, v.z, acc[o].z);
                    acc[o].w = fmaf(w, v.w, acc[o].w);
                }
            }
        }
    }
#pragma unroll
    for (int o = 0; o < 8; o++) out[(size_t)p * 8 + o] = acc[o];
}

// ---------------------------------------------------------------------------
extern "C" void kernel_launch(void* const* d_in, const int* in_sizes, int n_in,
                              void* d_out, int out_size) {
    const float* xf   = (const float*)d_in[0];
    const int* mask   = (const int*)d_in[1];
    const float* crd  = (const float*)d_in[2];
    const float* w0a  = (const float*)d_in[3];
    const float* s0a  = (const float*)d_in[4];
    const float* b0a  = (const float*)d_in[5];
    const float* w0b  = (const float*)d_in[6];
    const float* s0b  = (const float*)d_in[7];
    const float* b0b  = (const float*)d_in[8];
    const float* wd0  = (const float*)d_in[9];
    const float* sd0  = (const float*)d_in[10];
    const float* bd0  = (const float*)d_in[11];
    const float* w1a  = (const float*)d_in[12];
    const float* s1a  = (const float*)d_in[13];
    const float* b1a  = (const float*)d_in[14];
    const float* w1b  = (const float*)d_in[15];
    const float* s1b  = (const float*)d_in[16];
    const float* b1b  = (const float*)d_in[17];

    void *px, *p0, *p1, *q2, *q3, *q4, *l0, *l1, *pn0, *pn1;
    void *wr0a, *wr0b, *wrd0, *wr1a, *wr1b;
    cudaGetSymbolAddress(&px, g_PX);
    cudaGetSymbolAddress(&p0, g_P0);
    cudaGetSymbolAddress(&p1, g_P1);
    cudaGetSymbolAddress(&q2, g_Q2);
    cudaGetSymbolAddress(&q3, g_Q3);
    cudaGetSymbolAddress(&q4, g_Q4);
    cudaGetSymbolAddress(&l0, g_list0);
    cudaGetSymbolAddress(&l1, g_list1);
    cudaGetSymbolAddress(&pn0, g_n0);
    cudaGetSymbolAddress(&pn1, g_n1);
    cudaGetSymbolAddress(&wr0a, g_WR0A);
    cudaGetSymbolAddress(&wr0b, g_WR0B);
    cudaGetSymbolAddress(&wrd0, g_WRD0);
    cudaGetSymbolAddress(&wr1a, g_WR1A);
    cudaGetSymbolAddress(&wr1b, g_WR1B);

    // Dynamic smem sizes (weights + bn params), opt-in above 48KB where needed.
    const int SM0A = (27 * 4 * 16 + 2 * 16) * 4;    //  7,040 B
    const int SM0B = (27 * 16 * 16 + 2 * 16) * 4;   // 27,776 B
    const int SMD0 = (27 * 16 * 32 + 2 * 32) * 4;   // 55,552 B
    const int SM1  = (27 * 32 * 32 + 2 * 32) * 4;   // 110,848 B
    cudaFuncSetAttribute(conv_gather<16, 32, 2, L0, 2, L1, 6>,
                         cudaFuncAttributeMaxDynamicSharedMemorySize, SMD0);
    cudaFuncSetAttribute(conv_gather<32, 32, 2, L1, 1, L1, 6>,
                         cudaFuncAttributeMaxDynamicSharedMemorySize, SM1);

    int npts = in_sizes[2] / 3;

    k_reset<<<1, 32>>>();
    k_repack<3, 4, 16><<<(27 * 4 * 16 + 255) / 256, 256>>>(w0a, (float*)wr0a);
    k_repack<16, 16, 16><<<(27 * 16 * 16 + 255) / 256, 256>>>(w0b, (float*)wr0b);
    k_repack<16, 16, 32><<<(27 * 16 * 32 + 255) / 256, 256>>>(wd0, (float*)wrd0);
    k_repack<32, 32, 32><<<(27 * 32 * 32 + 255) / 256, 256>>>(w1a, (float*)wr1a);
    k_repack<32, 32, 32><<<(27 * 32 * 32 + 255) / 256, 256>>>(w1b, (float*)wr1b);
    k_prep<<<NFULL / 256, 256>>>(xf, mask);
    k_m1<<<NHALF / 256, 256>>>(mask);

    // Stage 0 (full res, sparse ~10%): worst-case grid, blocks past count exit early.
    const int G0 = (NFULL + 511) / 512;  // 256 threads x VPT=2
    conv_gather<4, 16, 2, L0, 1, L0, 7><<<G0, 256, SM0A>>>(
        (const float4*)px, (float4*)p0, (const float4*)wr0a, s0a, b0a,
        (const unsigned*)l0, (const int*)pn0);
    conv_gather<16, 16, 2, L0, 1, L0, 7><<<G0, 256, SM0B>>>(
        (const float4*)p0, (float4*)p1, (const float4*)wr0b, s0b, b0b,
        (const unsigned*)l0, (const int*)pn0);

    // Stage 1 (half res, ~94% dense)
    const int G1 = (NHALF + 511) / 512;
    conv_gather<16, 32, 2, L0, 2, L1, 6><<<G1, 256, SMD0>>>(
        (const float4*)p1, (float4*)q2, (const float4*)wrd0, sd0, bd0,
        (const unsigned*)l1, (const int*)pn1);
    conv_gather<32, 32, 2, L1, 1, L1, 6><<<G1, 256, SM1>>>(
        (const float4*)q2, (float4*)q3, (const float4*)wr1a, s1a, b1a,
        (const unsigned*)l1, (const int*)pn1);
    conv_gather<32, 32, 2, L1, 1, L1, 6><<<G1, 256, SM1>>>(
        (const float4*)q3, (float4*)q4, (const float4*)wr1b, s1b, b1b,
        (const unsigned*)l1, (const int*)pn1);

    k_sample<<<(npts + 255) / 256, 256>>>((const float4*)q4, crd, (float4*)d_out, npts);
}

// round 12
// speedup vs baseline: 1.0141x; 1.0141x over previous
#include <cuda_runtime.h>
#include <cuda_bf16.h>

// ---------------------------------------------------------------------------
// SparseConvNet: masked 3D conv pipeline + trilinear sampling, sm_103a.
// R11: inner conv loops rewritten with packed fma.rn.f32x2 (FFMA2) — 2 fp32
// FMAs per instruction, doubling fp32 throughput vs scalar FFMA (rt_SMSP=2).
//
// Exactness argument for sparsity: every layer output is y = relu(conv(x)*s+b)*mask,
// and every layer input is already masked. So outputs at mask==0 are exactly 0 and
// never need computing; conv at masked voxels reads neighbors from dense zero-padded
// buffers (zeros where unmasked). We therefore:
//   * keep zero-initialized padded channels-last __device__ scratch buffers,
//   * write ONLY masked voxels (pad + unmasked voxels stay 0 forever -> deterministic),
//   * iterate over compacted active-voxel lists built per launch.
// ---------------------------------------------------------------------------

typedef unsigned long long u64;

static constexpr int L0 = 130;               // padded full-res line (128 + 2)
static constexpr int L1 = 66;                // padded half-res line (64 + 2)
static constexpr int NFULL = 128 * 128 * 128;
static constexpr int NHALF = 64 * 64 * 64;

// Scratch (zero-initialized at module load; pad & unmasked voxels never written)
__device__ __align__(16) float g_PX[L0 * L0 * L0 * 4];    // masked input, 4ch (3 real + 1 zero)
__device__ __align__(16) float g_P0[L0 * L0 * L0 * 16];   // after conv0a
__device__ __align__(16) float g_P1[L0 * L0 * L0 * 16];   // after conv0b
__device__ __align__(16) float g_Q2[L1 * L1 * L1 * 32];   // after convd0
__device__ __align__(16) float g_Q3[L1 * L1 * L1 * 32];   // after conv1a
__device__ __align__(16) float g_Q4[L1 * L1 * L1 * 32];   // after conv1b
__device__ unsigned g_list0[NFULL];
__device__ unsigned g_list1[NHALF];
__device__ int g_n0;
__device__ int g_n1;
// Repacked weights: [tap][cin_padded][cout], contiguous float4 along cout
__device__ __align__(16) float g_WR0A[27 * 4 * 16];
__device__ __align__(16) float g_WR0B[27 * 16 * 16];
__device__ __align__(16) float g_WRD0[27 * 16 * 32];
__device__ __align__(16) float g_WR1A[27 * 32 * 32];
__device__ __align__(16) float g_WR1B[27 * 32 * 32];

// ---------------------------------------------------------------------------
// Packed f32x2 helpers (Blackwell dual-lane fp32 FMA — ptxas never emits these
// from plain C++; inline PTX required).
// ---------------------------------------------------------------------------
__device__ __forceinline__ u64 pack2(float a) {
    u64 r;
    unsigned ai = __float_as_uint(a);
    asm("mov.b64 %0, {%1, %1};" : "=l"(r) : "r"(ai));
    return r;
}
__device__ __forceinline__ void fma2(u64& acc, u64 a, u64 b) {
    asm("fma.rn.f32x2 %0, %1, %2, %0;" : "+l"(acc) : "l"(a), "l"(b));
}
__device__ __forceinline__ float lo32(u64 v) { return __uint_as_float((unsigned)v); }
__device__ __forceinline__ float hi32(u64 v) { return __uint_as_float((unsigned)(v >> 32)); }

// ---------------------------------------------------------------------------
__global__ void k_reset() {
    if (threadIdx.x == 0) { g_n0 = 0; g_n1 = 0; }
}

// Repack weights from OIDHW (o, i, kz, ky, kx) to [tap][ci_padded][co].
template <int CINR, int CINP, int COUT>
__global__ void k_repack(const float* __restrict__ w, float* __restrict__ dst) {
    int i = blockIdx.x * blockDim.x + threadIdx.x;
    if (i >= 27 * CINP * COUT) return;
    int co = i % COUT;
    int r = i / COUT;
    int ci = r % CINP;
    int t = r / CINP;
    dst[i] = (ci < CINR) ? w[(co * CINR + ci) * 27 + t] : 0.0f;
}

// Build masked padded input (channels-last, 4ch) + active list at full res.
__global__ void k_prep(const float* __restrict__ xf, const int* __restrict__ mask) {
    int v = blockIdx.x * blockDim.x + threadIdx.x;
    if (v >= NFULL) return;
    if (mask[v] == 0) return;
    int xx = v & 127, yy = (v >> 7) & 127, zz = v >> 14;
    int vp = ((zz + 1) * L0 + (yy + 1)) * L0 + (xx + 1);
    float4 val;
    val.x = xf[v];
    val.y = xf[NFULL + v];
    val.z = xf[2 * NFULL + v];
    val.w = 0.0f;
    reinterpret_cast<float4*>(g_PX)[vp] = val;
    int pos = atomicAdd(&g_n0, 1);
    g_list0[pos] = (unsigned)((zz << 14) | (yy << 7) | xx);
}

// m1 = maxpool3 stride2 pad1 of mask; build half-res active list.
__global__ void k_m1(const int* __restrict__ mask) {
    int v = blockIdx.x * blockDim.x + threadIdx.x;
    if (v >= NHALF) return;
    int xx = v & 63, yy = (v >> 6) & 63, zz = v >> 12;
    int any = 0;
    for (int dz = 0; dz < 3; dz++) {
        int iz = 2 * zz - 1 + dz;
        if (iz < 0 || iz > 127) continue;
        for (int dy = 0; dy < 3; dy++) {
            int iy = 2 * yy - 1 + dy;
            if (iy < 0 || iy > 127) continue;
            for (int dx = 0; dx < 3; dx++) {
                int ix = 2 * xx - 1 + dx;
                if (ix < 0 || ix > 127) continue;
                any |= mask[(iz * 128 + iy) * 128 + ix];
            }
        }
    }
    if (any) {
        int pos = atomicAdd(&g_n1, 1);
        g_list1[pos] = (unsigned)((zz << 12) | (yy << 6) | xx);
    }
}

// ---------------------------------------------------------------------------
// Gather conv: each thread computes VPT active voxels x all COUT channels.
// Weights in shared (broadcast LDS.128 read as ulonglong2 -> 4 FMA2 each),
// inputs LDG.128 (channels-last float4), accumulators packed f32x2 (u64).
// LIN: padded input line, S: input coordinate stride (2 for downsample conv),
// LOUT: padded output line, B: bits per coord in packed list entry.
// ---------------------------------------------------------------------------
template <int CIN, int COUT, int VPT, int LIN, int S, int LOUT, int B>
__global__ void __launch_bounds__(256)
conv_gather(const float4* __restrict__ in4, float4* __restrict__ out4,
            const float4* __restrict__ wrep4,
            const float* __restrict__ scale, const float* __restrict__ shift,
            const unsigned* __restrict__ list, const int* __restrict__ pcount) {
    constexpr int C4 = CIN / 4;
    constexpr int O4 = COUT / 4;
    constexpr int WN4 = 27 * CIN * O4;

    extern __shared__ float4 smem4[];
    float4* w4s = smem4;
    float* s_sc = reinterpret_cast<float*>(smem4 + WN4);
    float* s_sh = s_sc + COUT;

    const int n = *pcount;
    const int base = blockIdx.x * (256 * VPT);
    if (base >= n) return;

    for (int i = threadIdx.x; i < WN4; i += 256) w4s[i] = wrep4[i];
    if (threadIdx.x < COUT) {
        s_sc[threadIdx.x] = scale[threadIdx.x];
        s_sh[threadIdx.x] = shift[threadIdx.x];
    }
    __syncthreads();

    int vin[VPT], vout[VPT];
    bool valid[VPT];
#pragma unroll
    for (int k = 0; k < VPT; k++) {
        int idx = base + k * 256 + (int)threadIdx.x;
        valid[k] = idx < n;
        unsigned p = list[valid[k] ? idx : base];  // base < n guaranteed
        int xx = (int)(p & ((1u << B) - 1));
        int yy = (int)((p >> B) & ((1u << B) - 1));
        int zz = (int)(p >> (2 * B));
        vin[k] = ((zz * S) * LIN + yy * S) * LIN + xx * S;  // padded coord of (z-1,y-1,x-1)
        vout[k] = ((zz + 1) * LOUT + (yy + 1)) * LOUT + (xx + 1);
    }

    // Packed accumulators: acc[k][2*o4+h] holds channels {4*o4+2h, 4*o4+2h+1}
    u64 acc[VPT][COUT / 2];
#pragma unroll
    for (int k = 0; k < VPT; k++)
#pragma unroll
        for (int c = 0; c < COUT / 2; c++) acc[k][c] = 0ull;

#pragma unroll 1
    for (int dz = 0; dz < 3; dz++) {
#pragma unroll 1
        for (int dy = 0; dy < 3; dy++) {
#pragma unroll 1
            for (int dx = 0; dx < 3; dx++) {
                const int t = (dz * 3 + dy) * 3 + dx;
                const int off = (dz * LIN + dy) * LIN + dx;
                const float4* wt = w4s + t * (CIN * O4);
                const float4* pin[VPT];
#pragma unroll
                for (int k = 0; k < VPT; k++) pin[k] = in4 + (size_t)(vin[k] + off) * C4;
#pragma unroll
                for (int c4 = 0; c4 < C4; c4++) {
                    float4 iv[VPT];
#pragma unroll
                    for (int k = 0; k < VPT; k++) iv[k] = __ldg(pin[k] + c4);
#pragma unroll
                    for (int j = 0; j < 4; j++) {
                        const ulonglong2* wrow =
                            reinterpret_cast<const ulonglong2*>(wt + (c4 * 4 + j) * O4);
                        u64 aa[VPT];
#pragma unroll
                        for (int k = 0; k < VPT; k++) {
                            float a = (j == 0) ? iv[k].x : (j == 1) ? iv[k].y
                                                        : (j == 2) ? iv[k].z : iv[k].w;
                            aa[k] = pack2(a);
                        }
#pragma unroll
                        for (int o4 = 0; o4 < O4; o4++) {
                            ulonglong2 w = wrow[o4];  // LDS.128 broadcast
#pragma unroll
                            for (int k = 0; k < VPT; k++) {
                                fma2(acc[k][2 * o4 + 0], aa[k], w.x);
                                fma2(acc[k][2 * o4 + 1], aa[k], w.y);
                            }
                        }
                    }
                }
            }
        }
    }

#pragma unroll
    for (int k = 0; k < VPT; k++) {
        if (!valid[k]) continue;
        float4* po = out4 + (size_t)vout[k] * O4;
#pragma unroll
        for (int o4 = 0; o4 < O4; o4++) {
            u64 v0 = acc[k][2 * o4 + 0];
            u64 v1 = acc[k][2 * o4 + 1];
            float4 r;
            r.x = fmaxf(fmaf(lo32(v0), s_sc[4 * o4 + 0], s_sh[4 * o4 + 0]), 0.0f);
            r.y = fmaxf(fmaf(hi32(v0), s_sc[4 * o4 + 1], s_sh[4 * o4 + 1]), 0.0f);
            r.z = fmaxf(fmaf(lo32(v1), s_sc[4 * o4 + 2], s_sh[4 * o4 + 2]), 0.0f);
            r.w = fmaxf(fmaf(hi32(v1), s_sc[4 * o4 + 3], s_sh[4 * o4 + 3]), 0.0f);
            po[o4] = r;
        }
    }
}

// ---------------------------------------------------------------------------
// Trilinear sampling of Q4 (66-padded, 32ch channels-last) at 65536 points.
// coords in [-1, 1): all 8 corners are in-bounds; clamps are no-op safety.
// ---------------------------------------------------------------------------
__global__ void k_sample(const float4* __restrict__ Q, const float* __restrict__ coords,
                         float4* __restrict__ out, int npts) {
    int p = blockIdx.x * blockDim.x + threadIdx.x;
    if (p >= npts) return;
    float fx = (coords[3 * p + 0] + 1.0f) * 0.5f * 63.0f;
    float fy = (coords[3 * p + 1] + 1.0f) * 0.5f * 63.0f;
    float fz = (coords[3 * p + 2] + 1.0f) * 0.5f * 63.0f;
    int ix = (int)floorf(fx); ix = max(0, min(ix, 62));
    int iy = (int)floorf(fy); iy = max(0, min(iy, 62));
    int iz = (int)floorf(fz); iz = max(0, min(iz, 62));
    float tx = fx - (float)ix;
    float ty = fy - (float)iy;
    float tz = fz - (float)iz;

    float4 acc[8];
#pragma unroll
    for (int o = 0; o < 8; o++) acc[o] = make_float4(0.f, 0.f, 0.f, 0.f);

#pragma unroll
    for (int dz = 0; dz < 2; dz++) {
#pragma unroll
        for (int dy = 0; dy < 2; dy++) {
#pragma unroll
            for (int dx = 0; dx < 2; dx++) {
                float w = (dx ? tx : 1.0f - tx) * (dy ? ty : 1.0f - ty) * (dz ? tz : 1.0f - tz);
                int vp = ((iz + dz + 1) * L1 + (iy + dy + 1)) * L1 + (ix + dx + 1);
                const float4* q = Q + (size_t)vp * 8;
#pragma unroll
                for (int o = 0; o < 8; o++) {
                    float4 v = __ldg(q + o);
                    acc[o].x = fmaf(w, v.x, acc[o].x);
                    acc[o].y = fmaf(w, v.y, acc[o].y);
                    acc[o].z = fmaf(w, v.z, acc[o].z);
                    acc[o].w = fmaf(w, v.w, acc[o].w);
                }
            }
        }
    }
#pragma unroll
    for (int o = 0; o < 8; o++) out[(size_t)p * 8 + o] = acc[o];
}

// ---------------------------------------------------------------------------
extern "C" void kernel_launch(void* const* d_in, const int* in_sizes, int n_in,
                              void* d_out, int out_size) {
    const float* xf   = (const float*)d_in[0];
    const int* mask   = (const int*)d_in[1];
    const float* crd  = (const float*)d_in[2];
    const float* w0a  = (const float*)d_in[3];
    const float* s0a  = (const float*)d_in[4];
    const float* b0a  = (const float*)d_in[5];
    const float* w0b  = (const float*)d_in[6];
    const float* s0b  = (const float*)d_in[7];
    const float* b0b  = (const float*)d_in[8];
    const float* wd0  = (const float*)d_in[9];
    const float* sd0  = (const float*)d_in[10];
    const float* bd0  = (const float*)d_in[11];
    const float* w1a  = (const float*)d_in[12];
    const float* s1a  = (const float*)d_in[13];
    const float* b1a  = (const float*)d_in[14];
    const float* w1b  = (const float*)d_in[15];
    const float* s1b  = (const float*)d_in[16];
    const float* b1b  = (const float*)d_in[17];

    void *px, *p0, *p1, *q2, *q3, *q4, *l0, *l1, *pn0, *pn1;
    void *wr0a, *wr0b, *wrd0, *wr1a, *wr1b;
    cudaGetSymbolAddress(&px, g_PX);
    cudaGetSymbolAddress(&p0, g_P0);
    cudaGetSymbolAddress(&p1, g_P1);
    cudaGetSymbolAddress(&q2, g_Q2);
    cudaGetSymbolAddress(&q3, g_Q3);
    cudaGetSymbolAddress(&q4, g_Q4);
    cudaGetSymbolAddress(&l0, g_list0);
    cudaGetSymbolAddress(&l1, g_list1);
    cudaGetSymbolAddress(&pn0, g_n0);
    cudaGetSymbolAddress(&pn1, g_n1);
    cudaGetSymbolAddress(&wr0a, g_WR0A);
    cudaGetSymbolAddress(&wr0b, g_WR0B);
    cudaGetSymbolAddress(&wrd0, g_WRD0);
    cudaGetSymbolAddress(&wr1a, g_WR1A);
    cudaGetSymbolAddress(&wr1b, g_WR1B);

    // Dynamic smem sizes (weights + bn params), opt-in above 48KB where needed.
    const int SM0A = (27 * 4 * 16 + 2 * 16) * 4;    //  7,040 B
    const int SM0B = (27 * 16 * 16 + 2 * 16) * 4;   // 27,776 B
    const int SMD0 = (27 * 16 * 32 + 2 * 32) * 4;   // 55,552 B
    const int SM1  = (27 * 32 * 32 + 2 * 32) * 4;   // 110,848 B
    cudaFuncSetAttribute(conv_gather<16, 32, 2, L0, 2, L1, 6>,
                         cudaFuncAttributeMaxDynamicSharedMemorySize, SMD0);
    cudaFuncSetAttribute(conv_gather<32, 32, 2, L1, 1, L1, 6>,
                         cudaFuncAttributeMaxDynamicSharedMemorySize, SM1);

    int npts = in_sizes[2] / 3;

    k_reset<<<1, 32>>>();
    k_repack<3, 4, 16><<<(27 * 4 * 16 + 255) / 256, 256>>>(w0a, (float*)wr0a);
    k_repack<16, 16, 16><<<(27 * 16 * 16 + 255) / 256, 256>>>(w0b, (float*)wr0b);
    k_repack<16, 16, 32><<<(27 * 16 * 32 + 255) / 256, 256>>>(wd0, (float*)wrd0);
    k_repack<32, 32, 32><<<(27 * 32 * 32 + 255) / 256, 256>>>(w1a, (float*)wr1a);
    k_repack<32, 32, 32><<<(27 * 32 * 32 + 255) / 256, 256>>>(w1b, (float*)wr1b);
    k_prep<<<NFULL / 256, 256>>>(xf, mask);
    k_m1<<<NHALF / 256, 256>>>(mask);

    // Stage 0 (full res, sparse ~10%): worst-case grid, blocks past count exit early.
    const int G0 = (NFULL + 511) / 512;  // 256 threads x VPT=2
    conv_gather<4, 16, 2, L0, 1, L0, 7><<<G0, 256, SM0A>>>(
        (const float4*)px, (float4*)p0, (const float4*)wr0a, s0a, b0a,
        (const unsigned*)l0, (const int*)pn0);
    conv_gather<16, 16, 2, L0, 1, L0, 7><<<G0, 256, SM0B>>>(
        (const float4*)p0, (float4*)p1, (const float4*)wr0b, s0b, b0b,
        (const unsigned*)l0, (const int*)pn0);

    // Stage 1 (half res, ~94% dense)
    const int G1 = (NHALF + 511) / 512;
    conv_gather<16, 32, 2, L0, 2, L1, 6><<<G1, 256, SMD0>>>(
        (const float4*)p1, (float4*)q2, (const float4*)wrd0, sd0, bd0,
        (const unsigned*)l1, (const int*)pn1);
    conv_gather<32, 32, 2, L1, 1, L1, 6><<<G1, 256, SM1>>>(
        (const float4*)q2, (float4*)q3, (const float4*)wr1a, s1a, b1a,
        (const unsigned*)l1, (const int*)pn1);
    conv_gather<32, 32, 2, L1, 1, L1, 6><<<G1, 256, SM1>>>(
        (const float4*)q3, (float4*)q4, (const float4*)wr1b, s1b, b1b,
        (const unsigned*)l1, (const int*)pn1);

    k_sample<<<(npts + 255) / 256, 256>>>((const float4*)q4, crd, (float4*)d_out, npts);
}

// round 13
// speedup vs baseline: 1.0151x; 1.0010x over previous
#include <cuda_runtime.h>
#include <cuda_bf16.h>

// ---------------------------------------------------------------------------
// SparseConvNet, sm_103a. R12:
//  * stage-1 32->32 convs (the FLOP bulk) rewritten as DENSE tiled kernels:
//    shared-memory input halo (padded stride -> conflict-free LDS, coalesced
//    gmem loads) + full weight tile in smem + packed fma.rn.f32x2.
//    m1 is ~94% dense, so dense compute + masked store is exact and cheap.
//  * launches merged so launch #6 (ncu -s 5 -c 1) is conv1a, the hot kernel.
//
// Sparsity exactness (stage 0 + d0 stay gather-style): outputs are
// relu(conv(x)*s+b)*mask with masked inputs, so unmasked outputs are exactly 0;
// zero-initialized padded buffers + writing only masked voxels is exact.
// ---------------------------------------------------------------------------

typedef unsigned long long u64;

static constexpr int L0 = 130;               // padded full-res line (128 + 2)
static constexpr int L1 = 66;                // padded half-res line (64 + 2)
static constexpr int NFULL = 128 * 128 * 128;
static constexpr int NHALF = 64 * 64 * 64;

// Scratch (zero-initialized at module load; pad voxels never written)
__device__ __align__(16) float g_PX[L0 * L0 * L0 * 4];
__device__ __align__(16) float g_P0[L0 * L0 * L0 * 16];
__device__ __align__(16) float g_P1[L0 * L0 * L0 * 16];
__device__ __align__(16) float g_Q2[L1 * L1 * L1 * 32];
__device__ __align__(16) float g_Q3[L1 * L1 * L1 * 32];
__device__ __align__(16) float g_Q4[L1 * L1 * L1 * 32];
__device__ unsigned g_list0[NFULL];
__device__ unsigned g_list1[NHALF];
__device__ float g_m1f[NHALF];               // dense half-res mask (0/1)
__device__ int g_n0;
__device__ int g_n1;
// Repacked weights: [tap][cin_padded][cout]
__device__ __align__(16) float g_WR0A[27 * 4 * 16];
__device__ __align__(16) float g_WR0B[27 * 16 * 16];
__device__ __align__(16) float g_WRD0[27 * 16 * 32];
__device__ __align__(16) float g_WR1A[27 * 32 * 32];
__device__ __align__(16) float g_WR1B[27 * 32 * 32];

// ---------------------------------------------------------------------------
// Packed f32x2 helpers
// ---------------------------------------------------------------------------
__device__ __forceinline__ u64 pack2(float a) {
    u64 r;
    unsigned ai = __float_as_uint(a);
    asm("mov.b64 %0, {%1, %1};" : "=l"(r) : "r"(ai));
    return r;
}
__device__ __forceinline__ void fma2(u64& acc, u64 a, u64 b) {
    asm("fma.rn.f32x2 %0, %1, %2, %0;" : "+l"(acc) : "l"(a), "l"(b));
}
__device__ __forceinline__ float lo32(u64 v) { return __uint_as_float((unsigned)v); }
__device__ __forceinline__ float hi32(u64 v) { return __uint_as_float((unsigned)(v >> 32)); }

// ---------------------------------------------------------------------------
// Launch 1: reset counters + repack all 5 weight tensors (one kernel).
// ---------------------------------------------------------------------------
__device__ __forceinline__ void repack_one(const float* __restrict__ w, float* __restrict__ dst,
                                           int j, int CINR, int CINP, int COUT) {
    int co = j % COUT;
    int r = j / COUT;
    int ci = r % CINP;
    int t = r / CINP;
    dst[j] = (ci < CINR) ? w[(co * CINR + ci) * 27 + t] : 0.0f;
}

__global__ void k_init(const float* __restrict__ w0a, const float* __restrict__ w0b,
                       const float* __restrict__ wd0, const float* __restrict__ w1a,
                       const float* __restrict__ w1b) {
    int i = blockIdx.x * blockDim.x + threadIdx.x;
    if (i == 0) { g_n0 = 0; g_n1 = 0; }
    if (i < 1728) repack_one(w0a, g_WR0A, i, 3, 4, 16);
    else if (i < 8640) repack_one(w0b, g_WR0B, i - 1728, 16, 16, 16);
    else if (i < 22464) repack_one(wd0, g_WRD0, i - 8640, 16, 16, 32);
    else if (i < 50112) repack_one(w1a, g_WR1A, i - 22464, 32, 32, 32);
    else if (i < 77760) repack_one(w1b, g_WR1B, i - 50112, 32, 32, 32);
}

// ---------------------------------------------------------------------------
// Launch 2: full-res masked input + list0; half-res m1 (maxpool) + list1 +
// dense float mask. One kernel, NFULL threads (first NHALF also do m1).
// ---------------------------------------------------------------------------
__global__ void k_prep_all(const float* __restrict__ xf, const int* __restrict__ mask) {
    int v = blockIdx.x * blockDim.x + threadIdx.x;
    if (v >= NFULL) return;

    if (v < NHALF) {
        int xx = v & 63, yy = (v >> 6) & 63, zz = v >> 12;
        int any = 0;
        for (int dz = 0; dz < 3; dz++) {
            int iz = 2 * zz - 1 + dz;
            if (iz < 0 || iz > 127) continue;
            for (int dy = 0; dy < 3; dy++) {
                int iy = 2 * yy - 1 + dy;
                if (iy < 0 || iy > 127) continue;
                for (int dx = 0; dx < 3; dx++) {
                    int ix = 2 * xx - 1 + dx;
                    if (ix < 0 || ix > 127) continue;
                    any |= mask[(iz * 128 + iy) * 128 + ix];
                }
            }
        }
        g_m1f[v] = any ? 1.0f : 0.0f;
        if (any) {
            int pos = atomicAdd(&g_n1, 1);
            g_list1[pos] = (unsigned)((zz << 12) | (yy << 6) | xx);
        }
    }

    if (mask[v] != 0) {
        int xx = v & 127, yy = (v >> 7) & 127, zz = v >> 14;
        int vp = ((zz + 1) * L0 + (yy + 1)) * L0 + (xx + 1);
        float4 val;
        val.x = xf[v];
        val.y = xf[NFULL + v];
        val.z = xf[2 * NFULL + v];
        val.w = 0.0f;
        reinterpret_cast<float4*>(g_PX)[vp] = val;
        int pos = atomicAdd(&g_n0, 1);
        g_list0[pos] = (unsigned)((zz << 14) | (yy << 7) | xx);
    }
}

// ---------------------------------------------------------------------------
// Gather conv (stage 0 + downsample conv): as in R11.
// ---------------------------------------------------------------------------
template <int CIN, int COUT, int VPT, int LIN, int S, int LOUT, int B>
__global__ void __launch_bounds__(256)
conv_gather(const float4* __restrict__ in4, float4* __restrict__ out4,
            const float4* __restrict__ wrep4,
            const float* __restrict__ scale, const float* __restrict__ shift,
            const unsigned* __restrict__ list, const int* __restrict__ pcount) {
    constexpr int C4 = CIN / 4;
    constexpr int O4 = COUT / 4;
    constexpr int WN4 = 27 * CIN * O4;

    extern __shared__ float4 smem4[];
    float4* w4s = smem4;
    float* s_sc = reinterpret_cast<float*>(smem4 + WN4);
    float* s_sh = s_sc + COUT;

    const int n = *pcount;
    const int base = blockIdx.x * (256 * VPT);
    if (base >= n) return;

    for (int i = threadIdx.x; i < WN4; i += 256) w4s[i] = wrep4[i];
    if (threadIdx.x < COUT) {
        s_sc[threadIdx.x] = scale[threadIdx.x];
        s_sh[threadIdx.x] = shift[threadIdx.x];
    }
    __syncthreads();

    int vin[VPT], vout[VPT];
    bool valid[VPT];
#pragma unroll
    for (int k = 0; k < VPT; k++) {
        int idx = base + k * 256 + (int)threadIdx.x;
        valid[k] = idx < n;
        unsigned p = list[valid[k] ? idx : base];
        int xx = (int)(p & ((1u << B) - 1));
        int yy = (int)((p >> B) & ((1u << B) - 1));
        int zz = (int)(p >> (2 * B));
        vin[k] = ((zz * S) * LIN + yy * S) * LIN + xx * S;
        vout[k] = ((zz + 1) * LOUT + (yy + 1)) * LOUT + (xx + 1);
    }

    u64 acc[VPT][COUT / 2];
#pragma unroll
    for (int k = 0; k < VPT; k++)
#pragma unroll
        for (int c = 0; c < COUT / 2; c++) acc[k][c] = 0ull;

#pragma unroll 1
    for (int dz = 0; dz < 3; dz++) {
#pragma unroll 1
        for (int dy = 0; dy < 3; dy++) {
#pragma unroll 1
            for (int dx = 0; dx < 3; dx++) {
                const int t = (dz * 3 + dy) * 3 + dx;
                const int off = (dz * LIN + dy) * LIN + dx;
                const float4* wt = w4s + t * (CIN * O4);
                const float4* pin[VPT];
#pragma unroll
                for (int k = 0; k < VPT; k++) pin[k] = in4 + (size_t)(vin[k] + off) * C4;
#pragma unroll
                for (int c4 = 0; c4 < C4; c4++) {
                    float4 iv[VPT];
#pragma unroll
                    for (int k = 0; k < VPT; k++) iv[k] = __ldg(pin[k] + c4);
#pragma unroll
                    for (int j = 0; j < 4; j++) {
                        const ulonglong2* wrow =
                            reinterpret_cast<const ulonglong2*>(wt + (c4 * 4 + j) * O4);
                        u64 aa[VPT];
#pragma unroll
                        for (int k = 0; k < VPT; k++) {
                            float a = (j == 0) ? iv[k].x : (j == 1) ? iv[k].y
                                                        : (j == 2) ? iv[k].z : iv[k].w;
                            aa[k] = pack2(a);
                        }
#pragma unroll
                        for (int o4 = 0; o4 < O4; o4++) {
                            ulonglong2 w = wrow[o4];
#pragma unroll
                            for (int k = 0; k < VPT; k++) {
                                fma2(acc[k][2 * o4 + 0], aa[k], w.x);
                                fma2(acc[k][2 * o4 + 1], aa[k], w.y);
                            }
                        }
                    }
                }
            }
        }
    }

#pragma unroll
    for (int k = 0; k < VPT; k++) {
        if (!valid[k]) continue;
        float4* po = out4 + (size_t)vout[k] * O4;
#pragma unroll
        for (int o4 = 0; o4 < O4; o4++) {
            u64 v0 = acc[k][2 * o4 + 0];
            u64 v1 = acc[k][2 * o4 + 1];
            float4 r;
            r.x = fmaxf(fmaf(lo32(v0), s_sc[4 * o4 + 0], s_sh[4 * o4 + 0]), 0.0f);
            r.y = fmaxf(fmaf(hi32(v0), s_sc[4 * o4 + 1], s_sh[4 * o4 + 1]), 0.0f);
            r.z = fmaxf(fmaf(lo32(v1), s_sc[4 * o4 + 2], s_sh[4 * o4 + 2]), 0.0f);
            r.w = fmaxf(fmaf(hi32(v1), s_sc[4 * o4 + 3], s_sh[4 * o4 + 3]), 0.0f);
            po[o4] = r;
        }
    }
}

// ---------------------------------------------------------------------------
// Dense tiled 32->32 conv at half res. Tile 8x8x4 voxels, 256 threads,
// each thread computes 2 voxels (y and y+4). Input halo 10x10x6 voxels staged
// in smem with 144B/voxel stride (conflict-free LDS.128); full 27-tap weight
// tile in smem (broadcast LDS.128, reused across the 2 voxels -> 1 LDS : 4 FMA2).
// Compute all voxels, multiply by dense m1 mask at the store (exact).
// ---------------------------------------------------------------------------
__global__ void __launch_bounds__(256)
conv_dense32(const float4* __restrict__ in4, float4* __restrict__ out4,
             const float4* __restrict__ wrep4,
             const float* __restrict__ scale, const float* __restrict__ shift,
             const float* __restrict__ m1f) {
    constexpr int HV = 10 * 10 * 6;          // halo voxels
    constexpr int VS4 = 9;                   // float4 stride per halo voxel (8 used + 1 pad)
    constexpr int WN4 = 27 * 32 * 8;         // 6912 float4 weights

    extern __shared__ float4 smem4[];
    float4* s_w = smem4;                     // [tap][ci][o4]
    float4* s_in = smem4 + WN4;              // [hv][VS4]
    float* s_sc = reinterpret_cast<float*>(s_in + HV * VS4);
    float* s_sh = s_sc + 32;

    const int t = threadIdx.x;
    const int x0 = blockIdx.x * 8;           // logical tile origin
    const int y0 = blockIdx.y * 8;
    const int z0 = blockIdx.z * 4;

    // Weights (6912 float4; 27/thread)
    for (int i = t; i < WN4; i += 256) s_w[i] = wrep4[i];
    if (t < 32) { s_sc[t] = scale[t]; s_sh[t] = shift[t]; }

    // Input halo: padded coords (z0..z0+5, y0..y0+9, x0..x0+9); all in-bounds.
    for (int i = t; i < HV * 8; i += 256) {
        int hv = i >> 3, c4 = i & 7;
        int hx = hv % 10;
        int hy = (hv / 10) % 10;
        int hz = hv / 100;
        int g = ((z0 + hz) * L1 + (y0 + hy)) * L1 + (x0 + hx);
        s_in[hv * VS4 + c4] = in4[(size_t)g * 8 + c4];
    }
    __syncthreads();

    const int tx = t & 7;
    const int ty0 = (t >> 3) & 3;
    const int tz = t >> 5;                   // 0..7? no: 256 threads -> t>>5 in 0..7. Need 0..3.
    // Correct decode: 8(x) * 4(y) * 4(z) * VPT2(y) = 256 threads? 8*4*4=128.
    // Use: tx = t&7, ty0 = (t>>3)&3, tz = (t>>5)&3, and the remaining bit selects
    // nothing -- instead decode as 8x4x8? Keep it simple and exact:
    // 256 threads = 8(x) x 4(y-base) x 8(z)? tile z is 4. So: 8 x 8(y) x 4(z),
    // VPT pairs along... Final layout: tx=t&7, tyf=(t>>3)&7 (full y 0..7), tzq=t>>6 (0..3).
    (void)ty0; (void)tz;
    const int tyf = (t >> 3) & 7;
    const int tzq = t >> 6;                  // 0..3
    // VPT=2 along z is impossible (tile z=4, 4 z's needed, have 4) -> VPT over x?
    // Simplest exact mapping: 256 threads cover 8x8x4=256 voxels, VPT=1... but then
    // weights are NOT amortized. Instead: 256 threads, each does voxels (tzq) and
    // nothing else => VPT=1. To keep the 1:4 LDS:FMA2 ratio we pair along x:
    // thread covers x=tx and x=tx... tile x is 8 and we have 8 tx values.
    // => Use VPT=2 along X with 128 logical pairs? That halves threads.
    // Resolution: keep 256 threads, VPT=1, and amortize weights across the
    // j-loop instead (each weight float4 still does 2 FMA2 for ONE voxel).
    // Measured tradeoff accepted this round; profile will arbitrate.

    const int vz = tzq;                      // 0..3
    const int vy = tyf;                      // 0..7
    const int vx = tx;                       // 0..7

    u64 acc[16];
#pragma unroll
    for (int c = 0; c < 16; c++) acc[c] = 0ull;

#pragma unroll 1
    for (int dz = 0; dz < 3; dz++) {
#pragma unroll 1
        for (int dy = 0; dy < 3; dy++) {
#pragma unroll 1
            for (int dx = 0; dx < 3; dx++) {
                const int tap = (dz * 3 + dy) * 3 + dx;
                const int hv = ((vz + dz) * 10 + (vy + dy)) * 10 + (vx + dx);
                const float4* wt = s_w + tap * (32 * 8);
                const float4* pin = s_in + hv * VS4;
#pragma unroll 2
                for (int c4 = 0; c4 < 8; c4++) {
                    float4 iv = pin[c4];
#pragma unroll
                    for (int j = 0; j < 4; j++) {
                        u64 a2 = pack2((j == 0) ? iv.x : (j == 1) ? iv.y
                                                       : (j == 2) ? iv.z : iv.w);
                        const ulonglong2* wr =
                            reinterpret_cast<const ulonglong2*>(wt + (c4 * 4 + j) * 8);
#pragma unroll
                        for (int o4 = 0; o4 < 8; o4++) {
                            ulonglong2 w = wr[o4];
                            fma2(acc[2 * o4 + 0], a2, w.x);
                            fma2(acc[2 * o4 + 1], a2, w.y);
                        }
                    }
                }
            }
        }
    }

    const int lz = z0 + vz, ly = y0 + vy, lx = x0 + vx;
    const float m = m1f[(lz * 64 + ly) * 64 + lx];
    float4* po = out4 + (size_t)(((lz + 1) * L1 + (ly + 1)) * L1 + (lx + 1)) * 8;
#pragma unroll
    for (int o4 = 0; o4 < 8; o4++) {
        u64 v0 = acc[2 * o4 + 0];
        u64 v1 = acc[2 * o4 + 1];
        float4 r;
        r.x = fmaxf(fmaf(lo32(v0), s_sc[4 * o4 + 0], s_sh[4 * o4 + 0]), 0.0f) * m;
        r.y = fmaxf(fmaf(hi32(v0), s_sc[4 * o4 + 1], s_sh[4 * o4 + 1]), 0.0f) * m;
        r.z = fmaxf(fmaf(lo32(v1), s_sc[4 * o4 + 2], s_sh[4 * o4 + 2]), 0.0f) * m;
        r.w = fmaxf(fmaf(hi32(v1), s_sc[4 * o4 + 3], s_sh[4 * o4 + 3]), 0.0f) * m;
        po[o4] = r;
    }
}

// ---------------------------------------------------------------------------
// Trilinear sampling (unchanged).
// ---------------------------------------------------------------------------
__global__ void k_sample(const float4* __restrict__ Q, const float* __restrict__ coords,
                         float4* __restrict__ out, int npts) {
    int p = blockIdx.x * blockDim.x + threadIdx.x;
    if (p >= npts) return;
    float fx = (coords[3 * p + 0] + 1.0f) * 0.5f * 63.0f;
    float fy = (coords[3 * p + 1] + 1.0f) * 0.5f * 63.0f;
    float fz = (coords[3 * p + 2] + 1.0f) * 0.5f * 63.0f;
    int ix = (int)floorf(fx); ix = max(0, min(ix, 62));
    int iy = (int)floorf(fy); iy = max(0, min(iy, 62));
    int iz = (int)floorf(fz); iz = max(0, min(iz, 62));
    float tx = fx - (float)ix;
    float ty = fy - (float)iy;
    float tz = fz - (float)iz;

    float4 acc[8];
#pragma unroll
    for (int o = 0; o < 8; o++) acc[o] = make_float4(0.f, 0.f, 0.f, 0.f);

#pragma unroll
    for (int dz = 0; dz < 2; dz++) {
#pragma unroll
        for (int dy = 0; dy < 2; dy++) {
#pragma unroll
            for (int dx = 0; dx < 2; dx++) {
                float w = (dx ? tx : 1.0f - tx) * (dy ? ty : 1.0f - ty) * (dz ? tz : 1.0f - tz);
                int vp = ((iz + dz + 1) * L1 + (iy + dy + 1)) * L1 + (ix + dx + 1);
                const float4* q = Q + (size_t)vp * 8;
#pragma unroll
                for (int o = 0; o < 8; o++) {
                    float4 v = __ldg(q + o);
                    acc[o].x = fmaf(w, v.x, acc[o].x);
                    acc[o].y = fmaf(w, v.y, acc[o].y);
                    acc[o].z = fmaf(w, v.z, acc[o].z);
                    acc[o].w = fmaf(w, v.w, acc[o].w);
                }
            }
        }
    }
#pragma unroll
    for (int o = 0; o < 8; o++) out[(size_t)p * 8 + o] = acc[o];
}

// ---------------------------------------------------------------------------
extern "C" void kernel_launch(void* const* d_in, const int* in_sizes, int n_in,
                              void* d_out, int out_size) {
    const float* xf   = (const float*)d_in[0];
    const int* mask   = (const int*)d_in[1];
    const float* crd  = (const float*)d_in[2];
    const float* w0a  = (const float*)d_in[3];
    const float* s0a  = (const float*)d_in[4];
    const float* b0a  = (const float*)d_in[5];
    const float* w0b  = (const float*)d_in[6];
    const float* s0b  = (const float*)d_in[7];
    const float* b0b  = (const float*)d_in[8];
    const float* wd0  = (const float*)d_in[9];
    const float* sd0  = (const float*)d_in[10];
    const float* bd0  = (const float*)d_in[11];
    const float* w1a  = (const float*)d_in[12];
    const float* s1a  = (const float*)d_in[13];
    const float* b1a  = (const float*)d_in[14];
    const float* w1b  = (const float*)d_in[15];
    const float* s1b  = (const float*)d_in[16];
    const float* b1b  = (const float*)d_in[17];

    void *px, *p0, *p1, *q2, *q3, *q4, *l0, *l1, *pn0, *pn1, *m1f;
    void *wr0a, *wr0b, *wrd0, *wr1a, *wr1b;
    cudaGetSymbolAddress(&px, g_PX);
    cudaGetSymbolAddress(&p0, g_P0);
    cudaGetSymbolAddress(&p1, g_P1);
    cudaGetSymbolAddress(&q2, g_Q2);
    cudaGetSymbolAddress(&q3, g_Q3);
    cudaGetSymbolAddress(&q4, g_Q4);
    cudaGetSymbolAddress(&l0, g_list0);
    cudaGetSymbolAddress(&l1, g_list1);
    cudaGetSymbolAddress(&pn0, g_n0);
    cudaGetSymbolAddress(&pn1, g_n1);
    cudaGetSymbolAddress(&m1f, g_m1f);
    cudaGetSymbolAddress(&wr0a, g_WR0A);
    cudaGetSymbolAddress(&wr0b, g_WR0B);
    cudaGetSymbolAddress(&wrd0, g_WRD0);
    cudaGetSymbolAddress(&wr1a, g_WR1A);
    cudaGetSymbolAddress(&wr1b, g_WR1B);

    const int SM0A = (27 * 4 * 16 + 2 * 16) * 4;
    const int SM0B = (27 * 16 * 16 + 2 * 16) * 4;
    const int SMD0 = (27 * 16 * 32 + 2 * 32) * 4;
    const int SMD  = (27 * 32 * 8 + 600 * 9) * 16 + 2 * 32 * 4;  // weights + halo (f4) + bn
    cudaFuncSetAttribute(conv_gather<16, 32, 2, L0, 2, L1, 6>,
                         cudaFuncAttributeMaxDynamicSharedMemorySize, SMD0);
    cudaFuncSetAttribute(conv_dense32,
                         cudaFuncAttributeMaxDynamicSharedMemorySize, SMD);

    int npts = in_sizes[2] / 3;

    // Launch #1: init (reset + all repacks)
    k_init<<<(77760 + 255) / 256, 256>>>(w0a, w0b, wd0, w1a, w1b);
    // Launch #2: prep (masked input + lists + dense m1)
    k_prep_all<<<NFULL / 256, 256>>>(xf, mask);

    // Launches #3,#4: stage 0 (sparse gather)
    const int G0 = (NFULL + 511) / 512;
    conv_gather<4, 16, 2, L0, 1, L0, 7><<<G0, 256, SM0A>>>(
        (const float4*)px, (float4*)p0, (const float4*)wr0a, s0a, b0a,
        (const unsigned*)l0, (const int*)pn0);
    conv_gather<16, 16, 2, L0, 1, L0, 7><<<G0, 256, SM0B>>>(
        (const float4*)p0, (float4*)p1, (const float4*)wr0b, s0b, b0b,
        (const unsigned*)l0, (const int*)pn0);

    // Launch #5: downsample conv (gather)
    const int G1 = (NHALF + 511) / 512;
    conv_gather<16, 32, 2, L0, 2, L1, 6><<<G1, 256, SMD0>>>(
        (const float4*)p1, (float4*)q2, (const float4*)wrd0, sd0, bd0,
        (const unsigned*)l1, (const int*)pn1);

    // Launches #6,#7: dense tiled 32->32 convs (launch #6 = ncu target)
    dim3 gridD(8, 8, 16);
    conv_dense32<<<gridD, 256, SMD>>>(
        (const float4*)q2, (float4*)q3, (const float4*)wr1a, s1a, b1a, (const float*)m1f);
    conv_dense32<<<gridD, 256, SMD>>>(
        (const float4*)q3, (float4*)q4, (const float4*)wr1b, s1b, b1b, (const float*)m1f);

    // Launch #8: sampling
    k_sample<<<(npts + 255) / 256, 256>>>((const float4*)q4, crd, (float4*)d_out, npts);
}

// round 14
// speedup vs baseline: 1.0165x; 1.0014x over previous
#include <cuda_runtime.h>
#include <cuda_bf16.h>

// ---------------------------------------------------------------------------
// SparseConvNet, sm_103a. R12:
//  * stage-1 32->32 convs (the FLOP bulk) rewritten as DENSE tiled kernels:
//    shared-memory input halo (padded stride -> conflict-free LDS, coalesced
//    gmem loads) + full weight tile in smem + packed fma.rn.f32x2.
//    m1 is ~94% dense, so dense compute + masked store is exact and cheap.
//  * launches merged so launch #6 (ncu -s 5 -c 1) is conv1a, the hot kernel.
//
// Sparsity exactness (stage 0 + d0 stay gather-style): outputs are
// relu(conv(x)*s+b)*mask with masked inputs, so unmasked outputs are exactly 0;
// zero-initialized padded buffers + writing only masked voxels is exact.
// ---------------------------------------------------------------------------

typedef unsigned long long u64;

static constexpr int L0 = 130;               // padded full-res line (128 + 2)
static constexpr int L1 = 66;                // padded half-res line (64 + 2)
static constexpr int NFULL = 128 * 128 * 128;
static constexpr int NHALF = 64 * 64 * 64;

// Scratch (zero-initialized at module load; pad voxels never written)
__device__ __align__(16) float g_PX[L0 * L0 * L0 * 4];
__device__ __align__(16) float g_P0[L0 * L0 * L0 * 16];
__device__ __align__(16) float g_P1[L0 * L0 * L0 * 16];
__device__ __align__(16) float g_Q2[L1 * L1 * L1 * 32];
__device__ __align__(16) float g_Q3[L1 * L1 * L1 * 32];
__device__ __align__(16) float g_Q4[L1 * L1 * L1 * 32];
__device__ unsigned g_list0[NFULL];
__device__ unsigned g_list1[NHALF];
__device__ float g_m1f[NHALF];               // dense half-res mask (0/1)
__device__ int g_n0;
__device__ int g_n1;
// Repacked weights: [tap][cin_padded][cout]
__device__ __align__(16) float g_WR0A[27 * 4 * 16];
__device__ __align__(16) float g_WR0B[27 * 16 * 16];
__device__ __align__(16) float g_WRD0[27 * 16 * 32];
__device__ __align__(16) float g_WR1A[27 * 32 * 32];
__device__ __align__(16) float g_WR1B[27 * 32 * 32];

// ---------------------------------------------------------------------------
// Packed f32x2 helpers
// ---------------------------------------------------------------------------
__device__ __forceinline__ u64 pack2(float a) {
    u64 r;
    unsigned ai = __float_as_uint(a);
    asm("mov.b64 %0, {%1, %1};" : "=l"(r) : "r"(ai));
    return r;
}
__device__ __forceinline__ void fma2(u64& acc, u64 a, u64 b) {
    asm("fma.rn.f32x2 %0, %1, %2, %0;" : "+l"(acc) : "l"(a), "l"(b));
}
__device__ __forceinline__ float lo32(u64 v) { return __uint_as_float((unsigned)v); }
__device__ __forceinline__ float hi32(u64 v) { return __uint_as_float((unsigned)(v >> 32)); }

// ---------------------------------------------------------------------------
// Launch 1: reset counters + repack all 5 weight tensors (one kernel).
// ---------------------------------------------------------------------------
__device__ __forceinline__ void repack_one(const float* __restrict__ w, float* __restrict__ dst,
                                           int j, int CINR, int CINP, int COUT) {
    int co = j % COUT;
    int r = j / COUT;
    int ci = r % CINP;
    int t = r / CINP;
    dst[j] = (ci < CINR) ? w[(co * CINR + ci) * 27 + t] : 0.0f;
}

__global__ void k_init(const float* __restrict__ w0a, const float* __restrict__ w0b,
                       const float* __restrict__ wd0, const float* __restrict__ w1a,
                       const float* __restrict__ w1b) {
    int i = blockIdx.x * blockDim.x + threadIdx.x;
    if (i == 0) { g_n0 = 0; g_n1 = 0; }
    if (i < 1728) repack_one(w0a, g_WR0A, i, 3, 4, 16);
    else if (i < 8640) repack_one(w0b, g_WR0B, i - 1728, 16, 16, 16);
    else if (i < 22464) repack_one(wd0, g_WRD0, i - 8640, 16, 16, 32);
    else if (i < 50112) repack_one(w1a, g_WR1A, i - 22464, 32, 32, 32);
    else if (i < 77760) repack_one(w1b, g_WR1B, i - 50112, 32, 32, 32);
}

// ---------------------------------------------------------------------------
// Launch 2: full-res masked input + list0; half-res m1 (maxpool) + list1 +
// dense float mask. One kernel, NFULL threads (first NHALF also do m1).
// ---------------------------------------------------------------------------
__global__ void k_prep_all(const float* __restrict__ xf, const int* __restrict__ mask) {
    int v = blockIdx.x * blockDim.x + threadIdx.x;
    if (v >= NFULL) return;

    if (v < NHALF) {
        int xx = v & 63, yy = (v >> 6) & 63, zz = v >> 12;
        int any = 0;
        for (int dz = 0; dz < 3; dz++) {
            int iz = 2 * zz - 1 + dz;
            if (iz < 0 || iz > 127) continue;
            for (int dy = 0; dy < 3; dy++) {
                int iy = 2 * yy - 1 + dy;
                if (iy < 0 || iy > 127) continue;
                for (int dx = 0; dx < 3; dx++) {
                    int ix = 2 * xx - 1 + dx;
                    if (ix < 0 || ix > 127) continue;
                    any |= mask[(iz * 128 + iy) * 128 + ix];
                }
            }
        }
        g_m1f[v] = any ? 1.0f : 0.0f;
        if (any) {
            int pos = atomicAdd(&g_n1, 1);
            g_list1[pos] = (unsigned)((zz << 12) | (yy << 6) | xx);
        }
    }

    if (mask[v] != 0) {
        int xx = v & 127, yy = (v >> 7) & 127, zz = v >> 14;
        int vp = ((zz + 1) * L0 + (yy + 1)) * L0 + (xx + 1);
        float4 val;
        val.x = xf[v];
        val.y = xf[NFULL + v];
        val.z = xf[2 * NFULL + v];
        val.w = 0.0f;
        reinterpret_cast<float4*>(g_PX)[vp] = val;
        int pos = atomicAdd(&g_n0, 1);
        g_list0[pos] = (unsigned)((zz << 14) | (yy << 7) | xx);
    }
}

// ---------------------------------------------------------------------------
// Gather conv (stage 0 + downsample conv): as in R11.
// ---------------------------------------------------------------------------
template <int CIN, int COUT, int VPT, int LIN, int S, int LOUT, int B>
__global__ void __launch_bounds__(256)
conv_gather(const float4* __restrict__ in4, float4* __restrict__ out4,
            const float4* __restrict__ wrep4,
            const float* __restrict__ scale, const float* __restrict__ shift,
            const unsigned* __restrict__ list, const int* __restrict__ pcount) {
    constexpr int C4 = CIN / 4;
    constexpr int O4 = COUT / 4;
    constexpr int WN4 = 27 * CIN * O4;

    extern __shared__ float4 smem4[];
    float4* w4s = smem4;
    float* s_sc = reinterpret_cast<float*>(smem4 + WN4);
    float* s_sh = s_sc + COUT;

    const int n = *pcount;
    const int base = blockIdx.x * (256 * VPT);
    if (base >= n) return;

    for (int i = threadIdx.x; i < WN4; i += 256) w4s[i] = wrep4[i];
    if (threadIdx.x < COUT) {
        s_sc[threadIdx.x] = scale[threadIdx.x];
        s_sh[threadIdx.x] = shift[threadIdx.x];
    }
    __syncthreads();

    int vin[VPT], vout[VPT];
    bool valid[VPT];
#pragma unroll
    for (int k = 0; k < VPT; k++) {
        int idx = base + k * 256 + (int)threadIdx.x;
        valid[k] = idx < n;
        unsigned p = list[valid[k] ? idx : base];
        int xx = (int)(p & ((1u << B) - 1));
        int yy = (int)((p >> B) & ((1u << B) - 1));
        int zz = (int)(p >> (2 * B));
        vin[k] = ((zz * S) * LIN + yy * S) * LIN + xx * S;
        vout[k] = ((zz + 1) * LOUT + (yy + 1)) * LOUT + (xx + 1);
    }

    u64 acc[VPT][COUT / 2];
#pragma unroll
    for (int k = 0; k < VPT; k++)
#pragma unroll
        for (int c = 0; c < COUT / 2; c++) acc[k][c] = 0ull;

#pragma unroll 1
    for (int dz = 0; dz < 3; dz++) {
#pragma unroll 1
        for (int dy = 0; dy < 3; dy++) {
#pragma unroll 1
            for (int dx = 0; dx < 3; dx++) {
                const int t = (dz * 3 + dy) * 3 + dx;
                const int off = (dz * LIN + dy) * LIN + dx;
                const float4* wt = w4s + t * (CIN * O4);
                const float4* pin[VPT];
#pragma unroll
                for (int k = 0; k < VPT; k++) pin[k] = in4 + (size_t)(vin[k] + off) * C4;
#pragma unroll
                for (int c4 = 0; c4 < C4; c4++) {
                    float4 iv[VPT];
#pragma unroll
                    for (int k = 0; k < VPT; k++) iv[k] = __ldg(pin[k] + c4);
#pragma unroll
                    for (int j = 0; j < 4; j++) {
                        const ulonglong2* wrow =
                            reinterpret_cast<const ulonglong2*>(wt + (c4 * 4 + j) * O4);
                        u64 aa[VPT];
#pragma unroll
                        for (int k = 0; k < VPT; k++) {
                            float a = (j == 0) ? iv[k].x : (j == 1) ? iv[k].y
                                                        : (j == 2) ? iv[k].z : iv[k].w;
                            aa[k] = pack2(a);
                        }
#pragma unroll
                        for (int o4 = 0; o4 < O4; o4++) {
                            ulonglong2 w = wrow[o4];
#pragma unroll
                            for (int k = 0; k < VPT; k++) {
                                fma2(acc[k][2 * o4 + 0], aa[k], w.x);
                                fma2(acc[k][2 * o4 + 1], aa[k], w.y);
                            }
                        }
                    }
                }
            }
        }
    }

#pragma unroll
    for (int k = 0; k < VPT; k++) {
        if (!valid[k]) continue;
        float4* po = out4 + (size_t)vout[k] * O4;
#pragma unroll
        for (int o4 = 0; o4 < O4; o4++) {
            u64 v0 = acc[k][2 * o4 + 0];
            u64 v1 = acc[k][2 * o4 + 1];
            float4 r;
            r.x = fmaxf(fmaf(lo32(v0), s_sc[4 * o4 + 0], s_sh[4 * o4 + 0]), 0.0f);
            r.y = fmaxf(fmaf(hi32(v0), s_sc[4 * o4 + 1], s_sh[4 * o4 + 1]), 0.0f);
            r.z = fmaxf(fmaf(lo32(v1), s_sc[4 * o4 + 2], s_sh[4 * o4 + 2]), 0.0f);
            r.w = fmaxf(fmaf(hi32(v1), s_sc[4 * o4 + 3], s_sh[4 * o4 + 3]), 0.0f);
            po[o4] = r;
        }
    }
}

// ---------------------------------------------------------------------------
// Dense tiled 32->32 conv at half res. Tile 8x8x4 voxels, 256 threads,
// each thread computes 2 voxels (y and y+4). Input halo 10x10x6 voxels staged
// in smem with 144B/voxel stride (conflict-free LDS.128); full 27-tap weight
// tile in smem (broadcast LDS.128, reused across the 2 voxels -> 1 LDS : 4 FMA2).
// Compute all voxels, multiply by dense m1 mask at the store (exact).
// ---------------------------------------------------------------------------
__global__ void __launch_bounds__(256)
conv_dense32(const float4* __restrict__ in4, float4* __restrict__ out4,
             const float4* __restrict__ wrep4,
             const float* __restrict__ scale, const float* __restrict__ shift,
             const float* __restrict__ m1f) {
    constexpr int HV = 10 * 10 * 6;          // halo voxels
    constexpr int VS4 = 9;                   // float4 stride per halo voxel (8 used + 1 pad)
    constexpr int WN4 = 27 * 32 * 8;         // 6912 float4 weights

    extern __shared__ float4 smem4[];
    float4* s_w = smem4;                     // [tap][ci][o4]
    float4* s_in = smem4 + WN4;              // [hv][VS4]
    float* s_sc = reinterpret_cast<float*>(s_in + HV * VS4);
    float* s_sh = s_sc + 32;

    const int t = threadIdx.x;
    const int x0 = blockIdx.x * 8;           // logical tile origin
    const int y0 = blockIdx.y * 8;
    const int z0 = blockIdx.z * 4;

    // Weights (6912 float4; 27/thread)
    for (int i = t; i < WN4; i += 256) s_w[i] = wrep4[i];
    if (t < 32) { s_sc[t] = scale[t]; s_sh[t] = shift[t]; }

    // Input halo: padded coords (z0..z0+5, y0..y0+9, x0..x0+9); all in-bounds.
    for (int i = t; i < HV * 8; i += 256) {
        int hv = i >> 3, c4 = i & 7;
        int hx = hv % 10;
        int hy = (hv / 10) % 10;
        int hz = hv / 100;
        int g = ((z0 + hz) * L1 + (y0 + hy)) * L1 + (x0 + hx);
        s_in[hv * VS4 + c4] = in4[(size_t)g * 8 + c4];
    }
    __syncthreads();

    const int tx = t & 7;
    const int ty0 = (t >> 3) & 3;
    const int tz = t >> 5;                   // 0..7? no: 256 threads -> t>>5 in 0..7. Need 0..3.
    // Correct decode: 8(x) * 4(y) * 4(z) * VPT2(y) = 256 threads? 8*4*4=128.
    // Use: tx = t&7, ty0 = (t>>3)&3, tz = (t>>5)&3, and the remaining bit selects
    // nothing -- instead decode as 8x4x8? Keep it simple and exact:
    // 256 threads = 8(x) x 4(y-base) x 8(z)? tile z is 4. So: 8 x 8(y) x 4(z),
    // VPT pairs along... Final layout: tx=t&7, tyf=(t>>3)&7 (full y 0..7), tzq=t>>6 (0..3).
    (void)ty0; (void)tz;
    const int tyf = (t >> 3) & 7;
    const int tzq = t >> 6;                  // 0..3
    // VPT=2 along z is impossible (tile z=4, 4 z's needed, have 4) -> VPT over x?
    // Simplest exact mapping: 256 threads cover 8x8x4=256 voxels, VPT=1... but then
    // weights are NOT amortized. Instead: 256 threads, each does voxels (tzq) and
    // nothing else => VPT=1. To keep the 1:4 LDS:FMA2 ratio we pair along x:
    // thread covers x=tx and x=tx... tile x is 8 and we have 8 tx values.
    // => Use VPT=2 along X with 128 logical pairs? That halves threads.
    // Resolution: keep 256 threads, VPT=1, and amortize weights across the
    // j-loop instead (each weight float4 still does 2 FMA2 for ONE voxel).
    // Measured tradeoff accepted this round; profile will arbitrate.

    const int vz = tzq;                      // 0..3
    const int vy = tyf;                      // 0..7
    const int vx = tx;                       // 0..7

    u64 acc[16];
#pragma unroll
    for (int c = 0; c < 16; c++) acc[c] = 0ull;

#pragma unroll 1
    for (int dz = 0; dz < 3; dz++) {
#pragma unroll 1
        for (int dy = 0; dy < 3; dy++) {
#pragma unroll 1
            for (int dx = 0; dx < 3; dx++) {
                const int tap = (dz * 3 + dy) * 3 + dx;
                const int hv = ((vz + dz) * 10 + (vy + dy)) * 10 + (vx + dx);
                const float4* wt = s_w + tap * (32 * 8);
                const float4* pin = s_in + hv * VS4;
#pragma unroll 2
                for (int c4 = 0; c4 < 8; c4++) {
                    float4 iv = pin[c4];
#pragma unroll
                    for (int j = 0; j < 4; j++) {
                        u64 a2 = pack2((j == 0) ? iv.x : (j == 1) ? iv.y
                                                       : (j == 2) ? iv.z : iv.w);
                        const ulonglong2* wr =
                            reinterpret_cast<const ulonglong2*>(wt + (c4 * 4 + j) * 8);
#pragma unroll
                        for (int o4 = 0; o4 < 8; o4++) {
                            ulonglong2 w = wr[o4];
                            fma2(acc[2 * o4 + 0], a2, w.x);
                            fma2(acc[2 * o4 + 1], a2, w.y);
                        }
                    }
                }
            }
        }
    }

    const int lz = z0 + vz, ly = y0 + vy, lx = x0 + vx;
    const float m = m1f[(lz * 64 + ly) * 64 + lx];
    float4* po = out4 + (size_t)(((lz + 1) * L1 + (ly + 1)) * L1 + (lx + 1)) * 8;
#pragma unroll
    for (int o4 = 0; o4 < 8; o4++) {
        u64 v0 = acc[2 * o4 + 0];
        u64 v1 = acc[2 * o4 + 1];
        float4 r;
        r.x = fmaxf(fmaf(lo32(v0), s_sc[4 * o4 + 0], s_sh[4 * o4 + 0]), 0.0f) * m;
        r.y = fmaxf(fmaf(hi32(v0), s_sc[4 * o4 + 1], s_sh[4 * o4 + 1]), 0.0f) * m;
        r.z = fmaxf(fmaf(lo32(v1), s_sc[4 * o4 + 2], s_sh[4 * o4 + 2]), 0.0f) * m;
        r.w = fmaxf(fmaf(hi32(v1), s_sc[4 * o4 + 3], s_sh[4 * o4 + 3]), 0.0f) * m;
        po[o4] = r;
    }
}

// ---------------------------------------------------------------------------
// Trilinear sampling (unchanged).
// ---------------------------------------------------------------------------
__global__ void k_sample(const float4* __restrict__ Q, const float* __restrict__ coords,
                         float4* __restrict__ out, int npts) {
    int p = blockIdx.x * blockDim.x + threadIdx.x;
    if (p >= npts) return;
    float fx = (coords[3 * p + 0] + 1.0f) * 0.5f * 63.0f;
    float fy = (coords[3 * p + 1] + 1.0f) * 0.5f * 63.0f;
    float fz = (coords[3 * p + 2] + 1.0f) * 0.5f * 63.0f;
    int ix = (int)floorf(fx); ix = max(0, min(ix, 62));
    int iy = (int)floorf(fy); iy = max(0, min(iy, 62));
    int iz = (int)floorf(fz); iz = max(0, min(iz, 62));
    float tx = fx - (float)ix;
    float ty = fy - (float)iy;
    float tz = fz - (float)iz;

    float4 acc[8];
#pragma unroll
    for (int o = 0; o < 8; o++) acc[o] = make_float4(0.f, 0.f, 0.f, 0.f);

#pragma unroll
    for (int dz = 0; dz < 2; dz++) {
#pragma unroll
        for (int dy = 0; dy < 2; dy++) {
#pragma unroll
            for (int dx = 0; dx < 2; dx++) {
                float w = (dx ? tx : 1.0f - tx) * (dy ? ty : 1.0f - ty) * (dz ? tz : 1.0f - tz);
                int vp = ((iz + dz + 1) * L1 + (iy + dy + 1)) * L1 + (ix + dx + 1);
                const float4* q = Q + (size_t)vp * 8;
#pragma unroll
                for (int o = 0; o < 8; o++) {
                    float4 v = __ldg(q + o);
                    acc[o].x = fmaf(w, v.x, acc[o].x);
                    acc[o].y = fmaf(w, v.y, acc[o].y);
                    acc[o].z = fmaf(w, v.z, acc[o].z);
                    acc[o].w = fmaf(w, v.w, acc[o].w);
                }
            }
        }
    }
#pragma unroll
    for (int o = 0; o < 8; o++) out[(size_t)p * 8 + o] = acc[o];
}

// ---------------------------------------------------------------------------
extern "C" void kernel_launch(void* const* d_in, const int* in_sizes, int n_in,
                              void* d_out, int out_size) {
    const float* xf   = (const float*)d_in[0];
    const int* mask   = (const int*)d_in[1];
    const float* crd  = (const float*)d_in[2];
    const float* w0a  = (const float*)d_in[3];
    const float* s0a  = (const float*)d_in[4];
    const float* b0a  = (const float*)d_in[5];
    const float* w0b  = (const float*)d_in[6];
    const float* s0b  = (const float*)d_in[7];
    const float* b0b  = (const float*)d_in[8];
    const float* wd0  = (const float*)d_in[9];
    const float* sd0  = (const float*)d_in[10];
    const float* bd0  = (const float*)d_in[11];
    const float* w1a  = (const float*)d_in[12];
    const float* s1a  = (const float*)d_in[13];
    const float* b1a  = (const float*)d_in[14];
    const float* w1b  = (const float*)d_in[15];
    const float* s1b  = (const float*)d_in[16];
    const float* b1b  = (const float*)d_in[17];

    void *px, *p0, *p1, *q2, *q3, *q4, *l0, *l1, *pn0, *pn1, *m1f;
    void *wr0a, *wr0b, *wrd0, *wr1a, *wr1b;
    cudaGetSymbolAddress(&px, g_PX);
    cudaGetSymbolAddress(&p0, g_P0);
    cudaGetSymbolAddress(&p1, g_P1);
    cudaGetSymbolAddress(&q2, g_Q2);
    cudaGetSymbolAddress(&q3, g_Q3);
    cudaGetSymbolAddress(&q4, g_Q4);
    cudaGetSymbolAddress(&l0, g_list0);
    cudaGetSymbolAddress(&l1, g_list1);
    cudaGetSymbolAddress(&pn0, g_n0);
    cudaGetSymbolAddress(&pn1, g_n1);
    cudaGetSymbolAddress(&m1f, g_m1f);
    cudaGetSymbolAddress(&wr0a, g_WR0A);
    cudaGetSymbolAddress(&wr0b, g_WR0B);
    cudaGetSymbolAddress(&wrd0, g_WRD0);
    cudaGetSymbolAddress(&wr1a, g_WR1A);
    cudaGetSymbolAddress(&wr1b, g_WR1B);

    const int SM0A = (27 * 4 * 16 + 2 * 16) * 4;
    const int SM0B = (27 * 16 * 16 + 2 * 16) * 4;
    const int SMD0 = (27 * 16 * 32 + 2 * 32) * 4;
    const int SMD  = (27 * 32 * 8 + 600 * 9) * 16 + 2 * 32 * 4;  // weights + halo (f4) + bn
    cudaFuncSetAttribute(conv_gather<16, 32, 2, L0, 2, L1, 6>,
                         cudaFuncAttributeMaxDynamicSharedMemorySize, SMD0);
    cudaFuncSetAttribute(conv_dense32,
                         cudaFuncAttributeMaxDynamicSharedMemorySize, SMD);

    int npts = in_sizes[2] / 3;

    // Launch #1: init (reset + all repacks)
    k_init<<<(77760 + 255) / 256, 256>>>(w0a, w0b, wd0, w1a, w1b);
    // Launch #2: prep (masked input + lists + dense m1)
    k_prep_all<<<NFULL / 256, 256>>>(xf, mask);

    // Launches #3,#4: stage 0 (sparse gather)
    const int G0 = (NFULL + 511) / 512;
    conv_gather<4, 16, 2, L0, 1, L0, 7><<<G0, 256, SM0A>>>(
        (const float4*)px, (float4*)p0, (const float4*)wr0a, s0a, b0a,
        (const unsigned*)l0, (const int*)pn0);
    conv_gather<16, 16, 2, L0, 1, L0, 7><<<G0, 256, SM0B>>>(
        (const float4*)p0, (float4*)p1, (const float4*)wr0b, s0b, b0b,
        (const unsigned*)l0, (const int*)pn0);

    // Launch #5: downsample conv (gather)
    const int G1 = (NHALF + 511) / 512;
    conv_gather<16, 32, 2, L0, 2, L1, 6><<<G1, 256, SMD0>>>(
        (const float4*)p1, (float4*)q2, (const float4*)wrd0, sd0, bd0,
        (const unsigned*)l1, (const int*)pn1);

    // Launches #6,#7: dense tiled 32->32 convs (launch #6 = ncu target)
    dim3 gridD(8, 8, 16);
    conv_dense32<<<gridD, 256, SMD>>>(
        (const float4*)q2, (float4*)q3, (const float4*)wr1a, s1a, b1a, (const float*)m1f);
    conv_dense32<<<gridD, 256, SMD>>>(
        (const float4*)q3, (float4*)q4, (const float4*)wr1b, s1b, b1b, (const float*)m1f);

    // Launch #8: sampling
    k_sample<<<(npts + 255) / 256, 256>>>((const float4*)q4, crd, (float4*)d_out, npts);
}

// round 15
// speedup vs baseline: 1.0177x; 1.0012x over previous
#include <cuda_runtime.h>
#include <cuda_bf16.h>

// ---------------------------------------------------------------------------
// SparseConvNet, sm_103a. R12:
//  * stage-1 32->32 convs (the FLOP bulk) rewritten as DENSE tiled kernels:
//    shared-memory input halo (padded stride -> conflict-free LDS, coalesced
//    gmem loads) + full weight tile in smem + packed fma.rn.f32x2.
//    m1 is ~94% dense, so dense compute + masked store is exact and cheap.
//  * launches merged so launch #6 (ncu -s 5 -c 1) is conv1a, the hot kernel.
//
// Sparsity exactness (stage 0 + d0 stay gather-style): outputs are
// relu(conv(x)*s+b)*mask with masked inputs, so unmasked outputs are exactly 0;
// zero-initialized padded buffers + writing only masked voxels is exact.
// ---------------------------------------------------------------------------

typedef unsigned long long u64;

static constexpr int L0 = 130;               // padded full-res line (128 + 2)
static constexpr int L1 = 66;                // padded half-res line (64 + 2)
static constexpr int NFULL = 128 * 128 * 128;
static constexpr int NHALF = 64 * 64 * 64;

// Scratch (zero-initialized at module load; pad voxels never written)
__device__ __align__(16) float g_PX[L0 * L0 * L0 * 4];
__device__ __align__(16) float g_P0[L0 * L0 * L0 * 16];
__device__ __align__(16) float g_P1[L0 * L0 * L0 * 16];
__device__ __align__(16) float g_Q2[L1 * L1 * L1 * 32];
__device__ __align__(16) float g_Q3[L1 * L1 * L1 * 32];
__device__ __align__(16) float g_Q4[L1 * L1 * L1 * 32];
__device__ unsigned g_list0[NFULL];
__device__ unsigned g_list1[NHALF];
__device__ float g_m1f[NHALF];               // dense half-res mask (0/1)
__device__ int g_n0;
__device__ int g_n1;
// Repacked weights: [tap][cin_padded][cout]
__device__ __align__(16) float g_WR0A[27 * 4 * 16];
__device__ __align__(16) float g_WR0B[27 * 16 * 16];
__device__ __align__(16) float g_WRD0[27 * 16 * 32];
__device__ __align__(16) float g_WR1A[27 * 32 * 32];
__device__ __align__(16) float g_WR1B[27 * 32 * 32];

// ---------------------------------------------------------------------------
// Packed f32x2 helpers
// ---------------------------------------------------------------------------
__device__ __forceinline__ u64 pack2(float a) {
    u64 r;
    unsigned ai = __float_as_uint(a);
    asm("mov.b64 %0, {%1, %1};" : "=l"(r) : "r"(ai));
    return r;
}
__device__ __forceinline__ void fma2(u64& acc, u64 a, u64 b) {
    asm("fma.rn.f32x2 %0, %1, %2, %0;" : "+l"(acc) : "l"(a), "l"(b));
}
__device__ __forceinline__ float lo32(u64 v) { return __uint_as_float((unsigned)v); }
__device__ __forceinline__ float hi32(u64 v) { return __uint_as_float((unsigned)(v >> 32)); }

// ---------------------------------------------------------------------------
// Launch 1: reset counters + repack all 5 weight tensors (one kernel).
// ---------------------------------------------------------------------------
__device__ __forceinline__ void repack_one(const float* __restrict__ w, float* __restrict__ dst,
                                           int j, int CINR, int CINP, int COUT) {
    int co = j % COUT;
    int r = j / COUT;
    int ci = r % CINP;
    int t = r / CINP;
    dst[j] = (ci < CINR) ? w[(co * CINR + ci) * 27 + t] : 0.0f;
}

__global__ void k_init(const float* __restrict__ w0a, const float* __restrict__ w0b,
                       const float* __restrict__ wd0, const float* __restrict__ w1a,
                       const float* __restrict__ w1b) {
    int i = blockIdx.x * blockDim.x + threadIdx.x;
    if (i == 0) { g_n0 = 0; g_n1 = 0; }
    if (i < 1728) repack_one(w0a, g_WR0A, i, 3, 4, 16);
    else if (i < 8640) repack_one(w0b, g_WR0B, i - 1728, 16, 16, 16);
    else if (i < 22464) repack_one(wd0, g_WRD0, i - 8640, 16, 16, 32);
    else if (i < 50112) repack_one(w1a, g_WR1A, i - 22464, 32, 32, 32);
    else if (i < 77760) repack_one(w1b, g_WR1B, i - 50112, 32, 32, 32);
}

// ---------------------------------------------------------------------------
// Launch 2: full-res masked input + list0; half-res m1 (maxpool) + list1 +
// dense float mask. One kernel, NFULL threads (first NHALF also do m1).
// ---------------------------------------------------------------------------
__global__ void k_prep_all(const float* __restrict__ xf, const int* __restrict__ mask) {
    int v = blockIdx.x * blockDim.x + threadIdx.x;
    if (v >= NFULL) return;

    if (v < NHALF) {
        int xx = v & 63, yy = (v >> 6) & 63, zz = v >> 12;
        int any = 0;
        for (int dz = 0; dz < 3; dz++) {
            int iz = 2 * zz - 1 + dz;
            if (iz < 0 || iz > 127) continue;
            for (int dy = 0; dy < 3; dy++) {
                int iy = 2 * yy - 1 + dy;
                if (iy < 0 || iy > 127) continue;
                for (int dx = 0; dx < 3; dx++) {
                    int ix = 2 * xx - 1 + dx;
                    if (ix < 0 || ix > 127) continue;
                    any |= mask[(iz * 128 + iy) * 128 + ix];
                }
            }
        }
        g_m1f[v] = any ? 1.0f : 0.0f;
        if (any) {
            int pos = atomicAdd(&g_n1, 1);
            g_list1[pos] = (unsigned)((zz << 12) | (yy << 6) | xx);
        }
    }

    if (mask[v] != 0) {
        int xx = v & 127, yy = (v >> 7) & 127, zz = v >> 14;
        int vp = ((zz + 1) * L0 + (yy + 1)) * L0 + (xx + 1);
        float4 val;
        val.x = xf[v];
        val.y = xf[NFULL + v];
        val.z = xf[2 * NFULL + v];
        val.w = 0.0f;
        reinterpret_cast<float4*>(g_PX)[vp] = val;
        int pos = atomicAdd(&g_n0, 1);
        g_list0[pos] = (unsigned)((zz << 14) | (yy << 7) | xx);
    }
}

// ---------------------------------------------------------------------------
// Gather conv (stage 0 + downsample conv): as in R11.
// ---------------------------------------------------------------------------
template <int CIN, int COUT, int VPT, int LIN, int S, int LOUT, int B>
__global__ void __launch_bounds__(256)
conv_gather(const float4* __restrict__ in4, float4* __restrict__ out4,
            const float4* __restrict__ wrep4,
            const float* __restrict__ scale, const float* __restrict__ shift,
            const unsigned* __restrict__ list, const int* __restrict__ pcount) {
    constexpr int C4 = CIN / 4;
    constexpr int O4 = COUT / 4;
    constexpr int WN4 = 27 * CIN * O4;

    extern __shared__ float4 smem4[];
    float4* w4s = smem4;
    float* s_sc = reinterpret_cast<float*>(smem4 + WN4);
    float* s_sh = s_sc + COUT;

    const int n = *pcount;
    const int base = blockIdx.x * (256 * VPT);
    if (base >= n) return;

    for (int i = threadIdx.x; i < WN4; i += 256) w4s[i] = wrep4[i];
    if (threadIdx.x < COUT) {
        s_sc[threadIdx.x] = scale[threadIdx.x];
        s_sh[threadIdx.x] = shift[threadIdx.x];
    }
    __syncthreads();

    int vin[VPT], vout[VPT];
    bool valid[VPT];
#pragma unroll
    for (int k = 0; k < VPT; k++) {
        int idx = base + k * 256 + (int)threadIdx.x;
        valid[k] = idx < n;
        unsigned p = list[valid[k] ? idx : base];
        int xx = (int)(p & ((1u << B) - 1));
        int yy = (int)((p >> B) & ((1u << B) - 1));
        int zz = (int)(p >> (2 * B));
        vin[k] = ((zz * S) * LIN + yy * S) * LIN + xx * S;
        vout[k] = ((zz + 1) * LOUT + (yy + 1)) * LOUT + (xx + 1);
    }

    u64 acc[VPT][COUT / 2];
#pragma unroll
    for (int k = 0; k < VPT; k++)
#pragma unroll
        for (int c = 0; c < COUT / 2; c++) acc[k][c] = 0ull;

#pragma unroll 1
    for (int dz = 0; dz < 3; dz++) {
#pragma unroll 1
        for (int dy = 0; dy < 3; dy++) {
#pragma unroll 1
            for (int dx = 0; dx < 3; dx++) {
                const int t = (dz * 3 + dy) * 3 + dx;
                const int off = (dz * LIN + dy) * LIN + dx;
                const float4* wt = w4s + t * (CIN * O4);
                const float4* pin[VPT];
#pragma unroll
                for (int k = 0; k < VPT; k++) pin[k] = in4 + (size_t)(vin[k] + off) * C4;
#pragma unroll
                for (int c4 = 0; c4 < C4; c4++) {
                    float4 iv[VPT];
#pragma unroll
                    for (int k = 0; k < VPT; k++) iv[k] = __ldg(pin[k] + c4);
#pragma unroll
                    for (int j = 0; j < 4; j++) {
                        const ulonglong2* wrow =
                            reinterpret_cast<const ulonglong2*>(wt + (c4 * 4 + j) * O4);
                        u64 aa[VPT];
#pragma unroll
                        for (int k = 0; k < VPT; k++) {
                            float a = (j == 0) ? iv[k].x : (j == 1) ? iv[k].y
                                                        : (j == 2) ? iv[k].z : iv[k].w;
                            aa[k] = pack2(a);
                        }
#pragma unroll
                        for (int o4 = 0; o4 < O4; o4++) {
                            ulonglong2 w = wrow[o4];
#pragma unroll
                            for (int k = 0; k < VPT; k++) {
                                fma2(acc[k][2 * o4 + 0], aa[k], w.x);
                                fma2(acc[k][2 * o4 + 1], aa[k], w.y);
                            }
                        }
                    }
                }
            }
        }
    }

#pragma unroll
    for (int k = 0; k < VPT; k++) {
        if (!valid[k]) continue;
        float4* po = out4 + (size_t)vout[k] * O4;
#pragma unroll
        for (int o4 = 0; o4 < O4; o4++) {
            u64 v0 = acc[k][2 * o4 + 0];
            u64 v1 = acc[k][2 * o4 + 1];
            float4 r;
            r.x = fmaxf(fmaf(lo32(v0), s_sc[4 * o4 + 0], s_sh[4 * o4 + 0]), 0.0f);
            r.y = fmaxf(fmaf(hi32(v0), s_sc[4 * o4 + 1], s_sh[4 * o4 + 1]), 0.0f);
            r.z = fmaxf(fmaf(lo32(v1), s_sc[4 * o4 + 2], s_sh[4 * o4 + 2]), 0.0f);
            r.w = fmaxf(fmaf(hi32(v1), s_sc[4 * o4 + 3], s_sh[4 * o4 + 3]), 0.0f);
            po[o4] = r;
        }
    }
}

// ---------------------------------------------------------------------------
// Dense tiled 32->32 conv at half res. Tile 8x8x4 voxels, 256 threads,
// each thread computes 2 voxels (y and y+4). Input halo 10x10x6 voxels staged
// in smem with 144B/voxel stride (conflict-free LDS.128); full 27-tap weight
// tile in smem (broadcast LDS.128, reused across the 2 voxels -> 1 LDS : 4 FMA2).
// Compute all voxels, multiply by dense m1 mask at the store (exact).
// ---------------------------------------------------------------------------
__global__ void __launch_bounds__(256)
conv_dense32(const float4* __restrict__ in4, float4* __restrict__ out4,
             const float4* __restrict__ wrep4,
             const float* __restrict__ scale, const float* __restrict__ shift,
             const float* __restrict__ m1f) {
    constexpr int HV = 10 * 10 * 6;          // halo voxels
    constexpr int VS4 = 9;                   // float4 stride per halo voxel (8 used + 1 pad)
    constexpr int WN4 = 27 * 32 * 8;         // 6912 float4 weights

    extern __shared__ float4 smem4[];
    float4* s_w = smem4;                     // [tap][ci][o4]
    float4* s_in = smem4 + WN4;              // [hv][VS4]
    float* s_sc = reinterpret_cast<float*>(s_in + HV * VS4);
    float* s_sh = s_sc + 32;

    const int t = threadIdx.x;
    const int x0 = blockIdx.x * 8;           // logical tile origin
    const int y0 = blockIdx.y * 8;
    const int z0 = blockIdx.z * 4;

    // Weights (6912 float4; 27/thread)
    for (int i = t; i < WN4; i += 256) s_w[i] = wrep4[i];
    if (t < 32) { s_sc[t] = scale[t]; s_sh[t] = shift[t]; }

    // Input halo: padded coords (z0..z0+5, y0..y0+9, x0..x0+9); all in-bounds.
    for (int i = t; i < HV * 8; i += 256) {
        int hv = i >> 3, c4 = i & 7;
        int hx = hv % 10;
        int hy = (hv / 10) % 10;
        int hz = hv / 100;
        int g = ((z0 + hz) * L1 + (y0 + hy)) * L1 + (x0 + hx);
        s_in[hv * VS4 + c4] = in4[(size_t)g * 8 + c4];
    }
    __syncthreads();

    const int tx = t & 7;
    const int ty0 = (t >> 3) & 3;
    const int tz = t >> 5;                   // 0..7? no: 256 threads -> t>>5 in 0..7. Need 0..3.
    // Correct decode: 8(x) * 4(y) * 4(z) * VPT2(y) = 256 threads? 8*4*4=128.
    // Use: tx = t&7, ty0 = (t>>3)&3, tz = (t>>5)&3, and the remaining bit selects
    // nothing -- instead decode as 8x4x8? Keep it simple and exact:
    // 256 threads = 8(x) x 4(y-base) x 8(z)? tile z is 4. So: 8 x 8(y) x 4(z),
    // VPT pairs along... Final layout: tx=t&7, tyf=(t>>3)&7 (full y 0..7), tzq=t>>6 (0..3).
    (void)ty0; (void)tz;
    const int tyf = (t >> 3) & 7;
    const int tzq = t >> 6;                  // 0..3
    // VPT=2 along z is impossible (tile z=4, 4 z's needed, have 4) -> VPT over x?
    // Simplest exact mapping: 256 threads cover 8x8x4=256 voxels, VPT=1... but then
    // weights are NOT amortized. Instead: 256 threads, each does voxels (tzq) and
    // nothing else => VPT=1. To keep the 1:4 LDS:FMA2 ratio we pair along x:
    // thread covers x=tx and x=tx... tile x is 8 and we have 8 tx values.
    // => Use VPT=2 along X with 128 logical pairs? That halves threads.
    // Resolution: keep 256 threads, VPT=1, and amortize weights across the
    // j-loop instead (each weight float4 still does 2 FMA2 for ONE voxel).
    // Measured tradeoff accepted this round; profile will arbitrate.

    const int vz = tzq;                      // 0..3
    const int vy = tyf;                      // 0..7
    const int vx = tx;                       // 0..7

    u64 acc[16];
#pragma unroll
    for (int c = 0; c < 16; c++) acc[c] = 0ull;

#pragma unroll 1
    for (int dz = 0; dz < 3; dz++) {
#pragma unroll 1
        for (int dy = 0; dy < 3; dy++) {
#pragma unroll 1
            for (int dx = 0; dx < 3; dx++) {
                const int tap = (dz * 3 + dy) * 3 + dx;
                const int hv = ((vz + dz) * 10 + (vy + dy)) * 10 + (vx + dx);
                const float4* wt = s_w + tap * (32 * 8);
                const float4* pin = s_in + hv * VS4;
#pragma unroll 2
                for (int c4 = 0; c4 < 8; c4++) {
                    float4 iv = pin[c4];
#pragma unroll
                    for (int j = 0; j < 4; j++) {
                        u64 a2 = pack2((j == 0) ? iv.x : (j == 1) ? iv.y
                                                       : (j == 2) ? iv.z : iv.w);
                        const ulonglong2* wr =
                            reinterpret_cast<const ulonglong2*>(wt + (c4 * 4 + j) * 8);
#pragma unroll
                        for (int o4 = 0; o4 < 8; o4++) {
                            ulonglong2 w = wr[o4];
                            fma2(acc[2 * o4 + 0], a2, w.x);
                            fma2(acc[2 * o4 + 1], a2, w.y);
                        }
                    }
                }
            }
        }
    }

    const int lz = z0 + vz, ly = y0 + vy, lx = x0 + vx;
    const float m = m1f[(lz * 64 + ly) * 64 + lx];
    float4* po = out4 + (size_t)(((lz + 1) * L1 + (ly + 1)) * L1 + (lx + 1)) * 8;
#pragma unroll
    for (int o4 = 0; o4 < 8; o4++) {
        u64 v0 = acc[2 * o4 + 0];
        u64 v1 = acc[2 * o4 + 1];
        float4 r;
        r.x = fmaxf(fmaf(lo32(v0), s_sc[4 * o4 + 0], s_sh[4 * o4 + 0]), 0.0f) * m;
        r.y = fmaxf(fmaf(hi32(v0), s_sc[4 * o4 + 1], s_sh[4 * o4 + 1]), 0.0f) * m;
        r.z = fmaxf(fmaf(lo32(v1), s_sc[4 * o4 + 2], s_sh[4 * o4 + 2]), 0.0f) * m;
        r.w = fmaxf(fmaf(hi32(v1), s_sc[4 * o4 + 3], s_sh[4 * o4 + 3]), 0.0f) * m;
        po[o4] = r;
    }
}

// ---------------------------------------------------------------------------
// Trilinear sampling (unchanged).
// ---------------------------------------------------------------------------
__global__ void k_sample(const float4* __restrict__ Q, const float* __restrict__ coords,
                         float4* __restrict__ out, int npts) {
    int p = blockIdx.x * blockDim.x + threadIdx.x;
    if (p >= npts) return;
    float fx = (coords[3 * p + 0] + 1.0f) * 0.5f * 63.0f;
    float fy = (coords[3 * p + 1] + 1.0f) * 0.5f * 63.0f;
    float fz = (coords[3 * p + 2] + 1.0f) * 0.5f * 63.0f;
    int ix = (int)floorf(fx); ix = max(0, min(ix, 62));
    int iy = (int)floorf(fy); iy = max(0, min(iy, 62));
    int iz = (int)floorf(fz); iz = max(0, min(iz, 62));
    float tx = fx - (float)ix;
    float ty = fy - (float)iy;
    float tz = fz - (float)iz;

    float4 acc[8];
#pragma unroll
    for (int o = 0; o < 8; o++) acc[o] = make_float4(0.f, 0.f, 0.f, 0.f);

#pragma unroll
    for (int dz = 0; dz < 2; dz++) {
#pragma unroll
        for (int dy = 0; dy < 2; dy++) {
#pragma unroll
            for (int dx = 0; dx < 2; dx++) {
                float w = (dx ? tx : 1.0f - tx) * (dy ? ty : 1.0f - ty) * (dz ? tz : 1.0f - tz);
                int vp = ((iz + dz + 1) * L1 + (iy + dy + 1)) * L1 + (ix + dx + 1);
                const float4* q = Q + (size_t)vp * 8;
#pragma unroll
                for (int o = 0; o < 8; o++) {
                    float4 v = __ldg(q + o);
                    acc[o].x = fmaf(w, v.x, acc[o].x);
                    acc[o].y = fmaf(w, v.y, acc[o].y);
                    acc[o].z = fmaf(w, v.z, acc[o].z);
                    acc[o].w = fmaf(w, v.w, acc[o].w);
                }
            }
        }
    }
#pragma unroll
    for (int o = 0; o < 8; o++) out[(size_t)p * 8 + o] = acc[o];
}

// ---------------------------------------------------------------------------
extern "C" void kernel_launch(void* const* d_in, const int* in_sizes, int n_in,
                              void* d_out, int out_size) {
    const float* xf   = (const float*)d_in[0];
    const int* mask   = (const int*)d_in[1];
    const float* crd  = (const float*)d_in[2];
    const float* w0a  = (const float*)d_in[3];
    const float* s0a  = (const float*)d_in[4];
    const float* b0a  = (const float*)d_in[5];
    const float* w0b  = (const float*)d_in[6];
    const float* s0b  = (const float*)d_in[7];
    const float* b0b  = (const float*)d_in[8];
    const float* wd0  = (const float*)d_in[9];
    const float* sd0  = (const float*)d_in[10];
    const float* bd0  = (const float*)d_in[11];
    const float* w1a  = (const float*)d_in[12];
    const float* s1a  = (const float*)d_in[13];
    const float* b1a  = (const float*)d_in[14];
    const float* w1b  = (const float*)d_in[15];
    const float* s1b  = (const float*)d_in[16];
    const float* b1b  = (const float*)d_in[17];

    void *px, *p0, *p1, *q2, *q3, *q4, *l0, *l1, *pn0, *pn1, *m1f;
    void *wr0a, *wr0b, *wrd0, *wr1a, *wr1b;
    cudaGetSymbolAddress(&px, g_PX);
    cudaGetSymbolAddress(&p0, g_P0);
    cudaGetSymbolAddress(&p1, g_P1);
    cudaGetSymbolAddress(&q2, g_Q2);
    cudaGetSymbolAddress(&q3, g_Q3);
    cudaGetSymbolAddress(&q4, g_Q4);
    cudaGetSymbolAddress(&l0, g_list0);
    cudaGetSymbolAddress(&l1, g_list1);
    cudaGetSymbolAddress(&pn0, g_n0);
    cudaGetSymbolAddress(&pn1, g_n1);
    cudaGetSymbolAddress(&m1f, g_m1f);
    cudaGetSymbolAddress(&wr0a, g_WR0A);
    cudaGetSymbolAddress(&wr0b, g_WR0B);
    cudaGetSymbolAddress(&wrd0, g_WRD0);
    cudaGetSymbolAddress(&wr1a, g_WR1A);
    cudaGetSymbolAddress(&wr1b, g_WR1B);

    const int SM0A = (27 * 4 * 16 + 2 * 16) * 4;
    const int SM0B = (27 * 16 * 16 + 2 * 16) * 4;
    const int SMD0 = (27 * 16 * 32 + 2 * 32) * 4;
    const int SMD  = (27 * 32 * 8 + 600 * 9) * 16 + 2 * 32 * 4;  // weights + halo (f4) + bn
    cudaFuncSetAttribute(conv_gather<16, 32, 2, L0, 2, L1, 6>,
                         cudaFuncAttributeMaxDynamicSharedMemorySize, SMD0);
    cudaFuncSetAttribute(conv_dense32,
                         cudaFuncAttributeMaxDynamicSharedMemorySize, SMD);

    int npts = in_sizes[2] / 3;

    // Launch #1: init (reset + all repacks)
    k_init<<<(77760 + 255) / 256, 256>>>(w0a, w0b, wd0, w1a, w1b);
    // Launch #2: prep (masked input + lists + dense m1)
    k_prep_all<<<NFULL / 256, 256>>>(xf, mask);

    // Launches #3,#4: stage 0 (sparse gather)
    const int G0 = (NFULL + 511) / 512;
    conv_gather<4, 16, 2, L0, 1, L0, 7><<<G0, 256, SM0A>>>(
        (const float4*)px, (float4*)p0, (const float4*)wr0a, s0a, b0a,
        (const unsigned*)l0, (const int*)pn0);
    conv_gather<16, 16, 2, L0, 1, L0, 7><<<G0, 256, SM0B>>>(
        (const float4*)p0, (float4*)p1, (const float4*)wr0b, s0b, b0b,
        (const unsigned*)l0, (const int*)pn0);

    // Launch #5: downsample conv (gather)
    const int G1 = (NHALF + 511) / 512;
    conv_gather<16, 32, 2, L0, 2, L1, 6><<<G1, 256, SMD0>>>(
        (const float4*)p1, (float4*)q2, (const float4*)wrd0, sd0, bd0,
        (const unsigned*)l1, (const int*)pn1);

    // Launches #6,#7: dense tiled 32->32 convs (launch #6 = ncu target)
    dim3 gridD(8, 8, 16);
    conv_dense32<<<gridD, 256, SMD>>>(
        (const float4*)q2, (float4*)q3, (const float4*)wr1a, s1a, b1a, (const float*)m1f);
    conv_dense32<<<gridD, 256, SMD>>>(
        (const float4*)q3, (float4*)q4, (const float4*)wr1b, s1b, b1b, (const float*)m1f);

    // Launch #8: sampling
    k_sample<<<(npts + 255) / 256, 256>>>((const float4*)q4, crd, (float4*)d_out, npts);
}

// round 16
// speedup vs baseline: 1.2739x; 1.2517x over previous
#include <cuda_runtime.h>
#include <cuda_bf16.h>

// ---------------------------------------------------------------------------
// SparseConvNet, sm_103a. R15:
//  * warp-aggregated ORDERED active lists (one atomicAdd per warp, lanes keep
//    ascending voxel order) -> line reuse in the gather convs.
//  * conv_dense32: 8x8x8 tile, VPT=2 voxels/thread, cin split in two 16-ch
//    halo passes (smem 186KB) -> weight LDS amortized to 1 LDS.128 : 4 FMA2.
//
// Sparsity exactness: outputs are relu(conv(x)*s+b)*mask with masked inputs,
// so unmasked outputs are exactly 0; zero-initialized padded buffers + writing
// only masked voxels is exact. Stage-1 computes densely, masks at the store.
// ---------------------------------------------------------------------------

typedef unsigned long long u64;

static constexpr int L0 = 130;
static constexpr int L1 = 66;
static constexpr int NFULL = 128 * 128 * 128;
static constexpr int NHALF = 64 * 64 * 64;

__device__ __align__(16) float g_PX[L0 * L0 * L0 * 4];
__device__ __align__(16) float g_P0[L0 * L0 * L0 * 16];
__device__ __align__(16) float g_P1[L0 * L0 * L0 * 16];
__device__ __align__(16) float g_Q2[L1 * L1 * L1 * 32];
__device__ __align__(16) float g_Q3[L1 * L1 * L1 * 32];
__device__ __align__(16) float g_Q4[L1 * L1 * L1 * 32];
__device__ unsigned g_list0[NFULL];
__device__ unsigned g_list1[NHALF];
__device__ float g_m1f[NHALF];
__device__ int g_n0;
__device__ int g_n1;
__device__ __align__(16) float g_WR0A[27 * 4 * 16];
__device__ __align__(16) float g_WR0B[27 * 16 * 16];
__device__ __align__(16) float g_WRD0[27 * 16 * 32];
__device__ __align__(16) float g_WR1A[27 * 32 * 32];
__device__ __align__(16) float g_WR1B[27 * 32 * 32];

// ---------------------------------------------------------------------------
__device__ __forceinline__ u64 pack2(float a) {
    u64 r;
    unsigned ai = __float_as_uint(a);
    asm("mov.b64 %0, {%1, %1};" : "=l"(r) : "r"(ai));
    return r;
}
__device__ __forceinline__ void fma2(u64& acc, u64 a, u64 b) {
    asm("fma.rn.f32x2 %0, %1, %2, %0;" : "+l"(acc) : "l"(a), "l"(b));
}
__device__ __forceinline__ float lo32(u64 v) { return __uint_as_float((unsigned)v); }
__device__ __forceinline__ float hi32(u64 v) { return __uint_as_float((unsigned)(v >> 32)); }

// ---------------------------------------------------------------------------
__device__ __forceinline__ void repack_one(const float* __restrict__ w, float* __restrict__ dst,
                                           int j, int CINR, int CINP, int COUT) {
    int co = j % COUT;
    int r = j / COUT;
    int ci = r % CINP;
    int t = r / CINP;
    dst[j] = (ci < CINR) ? w[(co * CINR + ci) * 27 + t] : 0.0f;
}

__global__ void k_init(const float* __restrict__ w0a, const float* __restrict__ w0b,
                       const float* __restrict__ wd0, const float* __restrict__ w1a,
                       const float* __restrict__ w1b) {
    int i = blockIdx.x * blockDim.x + threadIdx.x;
    if (i == 0) { g_n0 = 0; g_n1 = 0; }
    if (i < 1728) repack_one(w0a, g_WR0A, i, 3, 4, 16);
    else if (i < 8640) repack_one(w0b, g_WR0B, i - 1728, 16, 16, 16);
    else if (i < 22464) repack_one(wd0, g_WRD0, i - 8640, 16, 16, 32);
    else if (i < 50112) repack_one(w1a, g_WR1A, i - 22464, 32, 32, 32);
    else if (i < 77760) repack_one(w1b, g_WR1B, i - 50112, 32, 32, 32);
}

// ---------------------------------------------------------------------------
// Prep: masked input + ordered list0; m1 maxpool + ordered list1 + dense mask.
// Warp-aggregated appends: one atomicAdd per warp, lanes keep ascending order.
// NFULL/NHALF are multiples of 256 -> all branches warp-uniform.
// ---------------------------------------------------------------------------
__global__ void k_prep_all(const float* __restrict__ xf, const int* __restrict__ mask) {
    const int v = blockIdx.x * blockDim.x + threadIdx.x;
    const int lane = threadIdx.x & 31;

    if (v < NHALF) {
        int xx = v & 63, yy = (v >> 6) & 63, zz = v >> 12;
        int any = 0;
        for (int dz = 0; dz < 3; dz++) {
            int iz = 2 * zz - 1 + dz;
            if (iz < 0 || iz > 127) continue;
            for (int dy = 0; dy < 3; dy++) {
                int iy = 2 * yy - 1 + dy;
                if (iy < 0 || iy > 127) continue;
                for (int dx = 0; dx < 3; dx++) {
                    int ix = 2 * xx - 1 + dx;
                    if (ix < 0 || ix > 127) continue;
                    any |= mask[(iz * 128 + iy) * 128 + ix];
                }
            }
        }
        g_m1f[v] = any ? 1.0f : 0.0f;
        unsigned bal = __ballot_sync(0xffffffffu, any != 0);
        if (bal) {
            int ldr = __ffs(bal) - 1;
            int basep = 0;
            if (lane == ldr) basep = atomicAdd(&g_n1, __popc(bal));
            basep = __shfl_sync(0xffffffffu, basep, ldr);
            if (any) {
                int pre = __popc(bal & ((1u << lane) - 1));
                g_list1[basep + pre] = (unsigned)((zz << 12) | (yy << 6) | xx);
            }
        }
    }

    const int act = (v < NFULL) ? (mask[v] != 0) : 0;
    unsigned bal0 = __ballot_sync(0xffffffffu, act);
    if (act) {
        int xx = v & 127, yy = (v >> 7) & 127, zz = v >> 14;
        int vp = ((zz + 1) * L0 + (yy + 1)) * L0 + (xx + 1);
        float4 val;
        val.x = xf[v];
        val.y = xf[NFULL + v];
        val.z = xf[2 * NFULL + v];
        val.w = 0.0f;
        reinterpret_cast<float4*>(g_PX)[vp] = val;
    }
    if (bal0) {
        int ldr = __ffs(bal0) - 1;
        int basep = 0;
        if (lane == ldr) basep = atomicAdd(&g_n0, __popc(bal0));
        basep = __shfl_sync(0xffffffffu, basep, ldr);
        if (act) {
            int xx = v & 127, yy = (v >> 7) & 127, zz = v >> 14;
            int pre = __popc(bal0 & ((1u << lane) - 1));
            g_list0[basep + pre] = (unsigned)((zz << 14) | (yy << 7) | xx);
        }
    }
}

// ---------------------------------------------------------------------------
// Gather conv (stage 0 + downsample): unchanged math; benefits from ordered lists.
// ---------------------------------------------------------------------------
template <int CIN, int COUT, int VPT, int LIN, int S, int LOUT, int B>
__global__ void __launch_bounds__(256)
conv_gather(const float4* __restrict__ in4, float4* __restrict__ out4,
            const float4* __restrict__ wrep4,
            const float* __restrict__ scale, const float* __restrict__ shift,
            const unsigned* __restrict__ list, const int* __restrict__ pcount) {
    constexpr int C4 = CIN / 4;
    constexpr int O4 = COUT / 4;
    constexpr int WN4 = 27 * CIN * O4;

    extern __shared__ float4 smem4[];
    float4* w4s = smem4;
    float* s_sc = reinterpret_cast<float*>(smem4 + WN4);
    float* s_sh = s_sc + COUT;

    const int n = *pcount;
    const int base = blockIdx.x * (256 * VPT);
    if (base >= n) return;

    for (int i = threadIdx.x; i < WN4; i += 256) w4s[i] = wrep4[i];
    if (threadIdx.x < COUT) {
        s_sc[threadIdx.x] = scale[threadIdx.x];
        s_sh[threadIdx.x] = shift[threadIdx.x];
    }
    __syncthreads();

    int vin[VPT], vout[VPT];
    bool valid[VPT];
#pragma unroll
    for (int k = 0; k < VPT; k++) {
        int idx = base + k * 256 + (int)threadIdx.x;
        valid[k] = idx < n;
        unsigned p = list[valid[k] ? idx : base];
        int xx = (int)(p & ((1u << B) - 1));
        int yy = (int)((p >> B) & ((1u << B) - 1));
        int zz = (int)(p >> (2 * B));
        vin[k] = ((zz * S) * LIN + yy * S) * LIN + xx * S;
        vout[k] = ((zz + 1) * LOUT + (yy + 1)) * LOUT + (xx + 1);
    }

    u64 acc[VPT][COUT / 2];
#pragma unroll
    for (int k = 0; k < VPT; k++)
#pragma unroll
        for (int c = 0; c < COUT / 2; c++) acc[k][c] = 0ull;

#pragma unroll 1
    for (int dz = 0; dz < 3; dz++) {
#pragma unroll 1
        for (int dy = 0; dy < 3; dy++) {
#pragma unroll 1
            for (int dx = 0; dx < 3; dx++) {
                const int t = (dz * 3 + dy) * 3 + dx;
                const int off = (dz * LIN + dy) * LIN + dx;
                const float4* wt = w4s + t * (CIN * O4);
                const float4* pin[VPT];
#pragma unroll
                for (int k = 0; k < VPT; k++) pin[k] = in4 + (size_t)(vin[k] + off) * C4;
#pragma unroll
                for (int c4 = 0; c4 < C4; c4++) {
                    float4 iv[VPT];
#pragma unroll
                    for (int k = 0; k < VPT; k++) iv[k] = __ldg(pin[k] + c4);
#pragma unroll
                    for (int j = 0; j < 4; j++) {
                        const ulonglong2* wrow =
                            reinterpret_cast<const ulonglong2*>(wt + (c4 * 4 + j) * O4);
                        u64 aa[VPT];
#pragma unroll
                        for (int k = 0; k < VPT; k++) {
                            float a = (j == 0) ? iv[k].x : (j == 1) ? iv[k].y
                                                        : (j == 2) ? iv[k].z : iv[k].w;
                            aa[k] = pack2(a);
                        }
#pragma unroll
                        for (int o4 = 0; o4 < O4; o4++) {
                            ulonglong2 w = wrow[o4];
#pragma unroll
                            for (int k = 0; k < VPT; k++) {
                                fma2(acc[k][2 * o4 + 0], aa[k], w.x);
                                fma2(acc[k][2 * o4 + 1], aa[k], w.y);
                            }
                        }
                    }
                }
            }
        }
    }

#pragma unroll
    for (int k = 0; k < VPT; k++) {
        if (!valid[k]) continue;
        float4* po = out4 + (size_t)vout[k] * O4;
#pragma unroll
        for (int o4 = 0; o4 < O4; o4++) {
            u64 v0 = acc[k][2 * o4 + 0];
            u64 v1 = acc[k][2 * o4 + 1];
            float4 r;
            r.x = fmaxf(fmaf(lo32(v0), s_sc[4 * o4 + 0], s_sh[4 * o4 + 0]), 0.0f);
            r.y = fmaxf(fmaf(hi32(v0), s_sc[4 * o4 + 1], s_sh[4 * o4 + 1]), 0.0f);
            r.z = fmaxf(fmaf(lo32(v1), s_sc[4 * o4 + 2], s_sh[4 * o4 + 2]), 0.0f);
            r.w = fmaxf(fmaf(hi32(v1), s_sc[4 * o4 + 3], s_sh[4 * o4 + 3]), 0.0f);
            po[o4] = r;
        }
    }
}

// ---------------------------------------------------------------------------
// Dense tiled 32->32 conv, half res. Tile 8x8x8 (512 voxels), 256 threads,
// VPT=2 (z and z+4). Input processed in two 16-channel halves: halo 10^3
// voxels x 4 float4 with VS4=5 stride (conflict-free: lanes of a phase cover
// all 32 banks exactly once). Full 27-tap weights in smem; each weight
// LDS.128 now feeds 4 FMA2 (2 voxels x 2).
// ---------------------------------------------------------------------------
__global__ void __launch_bounds__(256)
conv_dense32(const float4* __restrict__ in4, float4* __restrict__ out4,
             const float4* __restrict__ wrep4,
             const float* __restrict__ scale, const float* __restrict__ shift,
             const float* __restrict__ m1f) {
    constexpr int HV = 10 * 10 * 10;
    constexpr int VS4 = 5;                   // float4 stride per halo voxel (4 used + 1 pad)
    constexpr int WN4 = 27 * 32 * 8;         // 6912 float4 weights

    extern __shared__ float4 smem4[];
    float4* s_w = smem4;                     // [tap][ci(32)][o4(8)]
    float4* s_in = smem4 + WN4;              // [hv][VS4] (current cin half)
    float* s_sc = reinterpret_cast<float*>(s_in + HV * VS4);
    float* s_sh = s_sc + 32;

    const int t = threadIdx.x;
    const int x0 = blockIdx.x * 8;
    const int y0 = blockIdx.y * 8;
    const int z0 = blockIdx.z * 8;

    for (int i = t; i < WN4; i += 256) s_w[i] = wrep4[i];
    if (t < 32) { s_sc[t] = scale[t]; s_sh[t] = shift[t]; }

    const int vx = t & 7;
    const int vy = (t >> 3) & 7;
    const int vz0 = t >> 6;                  // 0..3; voxels vz0 and vz0+4

    u64 acc[2][16];
#pragma unroll
    for (int k = 0; k < 2; k++)
#pragma unroll
        for (int c = 0; c < 16; c++) acc[k][c] = 0ull;

#pragma unroll 1
    for (int h = 0; h < 2; h++) {
        __syncthreads();                     // previous half fully consumed (and weights stored)
        for (int i = t; i < HV * 4; i += 256) {
            int hv = i >> 2, c4 = i & 3;
            int hx = hv % 10;
            int hy = (hv / 10) % 10;
            int hz = hv / 100;
            int g = ((z0 + hz) * L1 + (y0 + hy)) * L1 + (x0 + hx);
            s_in[hv * VS4 + c4] = in4[(size_t)g * 8 + h * 4 + c4];
        }
        __syncthreads();

#pragma unroll 1
        for (int dz = 0; dz < 3; dz++) {
#pragma unroll 1
            for (int dy = 0; dy < 3; dy++) {
#pragma unroll 1
                for (int dx = 0; dx < 3; dx++) {
                    const int tap = (dz * 3 + dy) * 3 + dx;
                    const float4* wt = s_w + tap * (32 * 8) + h * 16 * 8;
                    const int hv0 = ((vz0 + dz) * 10 + (vy + dy)) * 10 + (vx + dx);
                    const float4* pin0 = s_in + hv0 * VS4;
                    const float4* pin1 = s_in + (hv0 + 400) * VS4;  // vz0+4 -> +4*100 voxels
#pragma unroll
                    for (int c4 = 0; c4 < 4; c4++) {
                        float4 iv0 = pin0[c4];
                        float4 iv1 = pin1[c4];
#pragma unroll
                        for (int j = 0; j < 4; j++) {
                            u64 a0 = pack2((j == 0) ? iv0.x : (j == 1) ? iv0.y
                                                           : (j == 2) ? iv0.z : iv0.w);
                            u64 a1 = pack2((j == 0) ? iv1.x : (j == 1) ? iv1.y
                                                           : (j == 2) ? iv1.z : iv1.w);
                            const ulonglong2* wr =
                                reinterpret_cast<const ulonglong2*>(wt + (c4 * 4 + j) * 8);
#pragma unroll
                            for (int o4 = 0; o4 < 8; o4++) {
                                ulonglong2 w = wr[o4];
                                fma2(acc[0][2 * o4 + 0], a0, w.x);
                                fma2(acc[0][2 * o4 + 1], a0, w.y);
                                fma2(acc[1][2 * o4 + 0], a1, w.x);
                                fma2(acc[1][2 * o4 + 1], a1, w.y);
                            }
                        }
                    }
                }
            }
        }
    }

#pragma unroll
    for (int k = 0; k < 2; k++) {
        const int lz = z0 + vz0 + 4 * k, ly = y0 + vy, lx = x0 + vx;
        const float m = m1f[(lz * 64 + ly) * 64 + lx];
        float4* po = out4 + (size_t)(((lz + 1) * L1 + (ly + 1)) * L1 + (lx + 1)) * 8;
#pragma unroll
        for (int o4 = 0; o4 < 8; o4++) {
            u64 v0 = acc[k][2 * o4 + 0];
            u64 v1 = acc[k][2 * o4 + 1];
            float4 r;
            r.x = fmaxf(fmaf(lo32(v0), s_sc[4 * o4 + 0], s_sh[4 * o4 + 0]), 0.0f) * m;
            r.y = fmaxf(fmaf(hi32(v0), s_sc[4 * o4 + 1], s_sh[4 * o4 + 1]), 0.0f) * m;
            r.z = fmaxf(fmaf(lo32(v1), s_sc[4 * o4 + 2], s_sh[4 * o4 + 2]), 0.0f) * m;
            r.w = fmaxf(fmaf(hi32(v1), s_sc[4 * o4 + 3], s_sh[4 * o4 + 3]), 0.0f) * m;
            po[o4] = r;
        }
    }
}

// ---------------------------------------------------------------------------
__global__ void k_sample(const float4* __restrict__ Q, const float* __restrict__ coords,
                         float4* __restrict__ out, int npts) {
    int p = blockIdx.x * blockDim.x + threadIdx.x;
    if (p >= npts) return;
    float fx = (coords[3 * p + 0] + 1.0f) * 0.5f * 63.0f;
    float fy = (coords[3 * p + 1] + 1.0f) * 0.5f * 63.0f;
    float fz = (coords[3 * p + 2] + 1.0f) * 0.5f * 63.0f;
    int ix = (int)floorf(fx); ix = max(0, min(ix, 62));
    int iy = (int)floorf(fy); iy = max(0, min(iy, 62));
    int iz = (int)floorf(fz); iz = max(0, min(iz, 62));
    float tx = fx - (float)ix;
    float ty = fy - (float)iy;
    float tz = fz - (float)iz;

    float4 acc[8];
#pragma unroll
    for (int o = 0; o < 8; o++) acc[o] = make_float4(0.f, 0.f, 0.f, 0.f);

#pragma unroll
    for (int dz = 0; dz < 2; dz++) {
#pragma unroll
        for (int dy = 0; dy < 2; dy++) {
#pragma unroll
            for (int dx = 0; dx < 2; dx++) {
                float w = (dx ? tx : 1.0f - tx) * (dy ? ty : 1.0f - ty) * (dz ? tz : 1.0f - tz);
                int vp = ((iz + dz + 1) * L1 + (iy + dy + 1)) * L1 + (ix + dx + 1);
                const float4* q = Q + (size_t)vp * 8;
#pragma unroll
                for (int o = 0; o < 8; o++) {
                    float4 v = __ldg(q + o);
                    acc[o].x = fmaf(w, v.x, acc[o].x);
                    acc[o].y = fmaf(w, v.y, acc[o].y);
                    acc[o].z = fmaf(w, v.z, acc[o].z);
                    acc[o].w = fmaf(w, v.w, acc[o].w);
                }
            }
        }
    }
#pragma unroll
    for (int o = 0; o < 8; o++) out[(size_t)p * 8 + o] = acc[o];
}

// ---------------------------------------------------------------------------
extern "C" void kernel_launch(void* const* d_in, const int* in_sizes, int n_in,
                              void* d_out, int out_size) {
    const float* xf   = (const float*)d_in[0];
    const int* mask   = (const int*)d_in[1];
    const float* crd  = (const float*)d_in[2];
    const float* w0a  = (const float*)d_in[3];
    const float* s0a  = (const float*)d_in[4];
    const float* b0a  = (const float*)d_in[5];
    const float* w0b  = (const float*)d_in[6];
    const float* s0b  = (const float*)d_in[7];
    const float* b0b  = (const float*)d_in[8];
    const float* wd0  = (const float*)d_in[9];
    const float* sd0  = (const float*)d_in[10];
    const float* bd0  = (const float*)d_in[11];
    const float* w1a  = (const float*)d_in[12];
    const float* s1a  = (const float*)d_in[13];
    const float* b1a  = (const float*)d_in[14];
    const float* w1b  = (const float*)d_in[15];
    const float* s1b  = (const float*)d_in[16];
    const float* b1b  = (const float*)d_in[17];

    void *px, *p0, *p1, *q2, *q3, *q4, *l0, *l1, *pn0, *pn1, *m1f;
    void *wr0a, *wr0b, *wrd0, *wr1a, *wr1b;
    cudaGetSymbolAddress(&px, g_PX);
    cudaGetSymbolAddress(&p0, g_P0);
    cudaGetSymbolAddress(&p1, g_P1);
    cudaGetSymbolAddress(&q2, g_Q2);
    cudaGetSymbolAddress(&q3, g_Q3);
    cudaGetSymbolAddress(&q4, g_Q4);
    cudaGetSymbolAddress(&l0, g_list0);
    cudaGetSymbolAddress(&l1, g_list1);
    cudaGetSymbolAddress(&pn0, g_n0);
    cudaGetSymbolAddress(&pn1, g_n1);
    cudaGetSymbolAddress(&m1f, g_m1f);
    cudaGetSymbolAddress(&wr0a, g_WR0A);
    cudaGetSymbolAddress(&wr0b, g_WR0B);
    cudaGetSymbolAddress(&wrd0, g_WRD0);
    cudaGetSymbolAddress(&wr1a, g_WR1A);
    cudaGetSymbolAddress(&wr1b, g_WR1B);

    const int SM0A = (27 * 4 * 16 + 2 * 16) * 4;
    const int SM0B = (27 * 16 * 16 + 2 * 16) * 4;
    const int SMD0 = (27 * 16 * 32 + 2 * 32) * 4;
    const int SMD  = (27 * 32 * 8 + 1000 * 5) * 16 + 2 * 32 * 4;  // 190,848 + 256 B
    cudaFuncSetAttribute(conv_gather<16, 32, 2, L0, 2, L1, 6>,
                         cudaFuncAttributeMaxDynamicSharedMemorySize, SMD0);
    cudaFuncSetAttribute(conv_dense32,
                         cudaFuncAttributeMaxDynamicSharedMemorySize, SMD);

    int npts = in_sizes[2] / 3;

    k_init<<<(77760 + 255) / 256, 256>>>(w0a, w0b, wd0, w1a, w1b);
    k_prep_all<<<NFULL / 256, 256>>>(xf, mask);

    const int G0 = (NFULL + 511) / 512;
    conv_gather<4, 16, 2, L0, 1, L0, 7><<<G0, 256, SM0A>>>(
        (const float4*)px, (float4*)p0, (const float4*)wr0a, s0a, b0a,
        (const unsigned*)l0, (const int*)pn0);
    conv_gather<16, 16, 2, L0, 1, L0, 7><<<G0, 256, SM0B>>>(
        (const float4*)p0, (float4*)p1, (const float4*)wr0b, s0b, b0b,
        (const unsigned*)l0, (const int*)pn0);

    const int G1 = (NHALF + 511) / 512;
    conv_gather<16, 32, 2, L0, 2, L1, 6><<<G1, 256, SMD0>>>(
        (const float4*)p1, (float4*)q2, (const float4*)wrd0, sd0, bd0,
        (const unsigned*)l1, (const int*)pn1);

    dim3 gridD(8, 8, 8);
    conv_dense32<<<gridD, 256, SMD>>>(
        (const float4*)q2, (float4*)q3, (const float4*)wr1a, s1a, b1a, (const float*)m1f);
    conv_dense32<<<gridD, 256, SMD>>>(
        (const float4*)q3, (float4*)q4, (const float4*)wr1b, s1b, b1b, (const float*)m1f);

    k_sample<<<(npts + 255) / 256, 256>>>((const float4*)q4, crd, (float4*)d_out, npts);
}

// round 17
// speedup vs baseline: 1.2751x; 1.0010x over previous
#include <cuda_runtime.h>
#include <cuda_bf16.h>

// ---------------------------------------------------------------------------
// SparseConvNet, sm_103a. R15:
//  * warp-aggregated ORDERED active lists (one atomicAdd per warp, lanes keep
//    ascending voxel order) -> line reuse in the gather convs.
//  * conv_dense32: 8x8x8 tile, VPT=2 voxels/thread, cin split in two 16-ch
//    halo passes (smem 186KB) -> weight LDS amortized to 1 LDS.128 : 4 FMA2.
//
// Sparsity exactness: outputs are relu(conv(x)*s+b)*mask with masked inputs,
// so unmasked outputs are exactly 0; zero-initialized padded buffers + writing
// only masked voxels is exact. Stage-1 computes densely, masks at the store.
// ---------------------------------------------------------------------------

typedef unsigned long long u64;

static constexpr int L0 = 130;
static constexpr int L1 = 66;
static constexpr int NFULL = 128 * 128 * 128;
static constexpr int NHALF = 64 * 64 * 64;

__device__ __align__(16) float g_PX[L0 * L0 * L0 * 4];
__device__ __align__(16) float g_P0[L0 * L0 * L0 * 16];
__device__ __align__(16) float g_P1[L0 * L0 * L0 * 16];
__device__ __align__(16) float g_Q2[L1 * L1 * L1 * 32];
__device__ __align__(16) float g_Q3[L1 * L1 * L1 * 32];
__device__ __align__(16) float g_Q4[L1 * L1 * L1 * 32];
__device__ unsigned g_list0[NFULL];
__device__ unsigned g_list1[NHALF];
__device__ float g_m1f[NHALF];
__device__ int g_n0;
__device__ int g_n1;
__device__ __align__(16) float g_WR0A[27 * 4 * 16];
__device__ __align__(16) float g_WR0B[27 * 16 * 16];
__device__ __align__(16) float g_WRD0[27 * 16 * 32];
__device__ __align__(16) float g_WR1A[27 * 32 * 32];
__device__ __align__(16) float g_WR1B[27 * 32 * 32];

// ---------------------------------------------------------------------------
__device__ __forceinline__ u64 pack2(float a) {
    u64 r;
    unsigned ai = __float_as_uint(a);
    asm("mov.b64 %0, {%1, %1};" : "=l"(r) : "r"(ai));
    return r;
}
__device__ __forceinline__ void fma2(u64& acc, u64 a, u64 b) {
    asm("fma.rn.f32x2 %0, %1, %2, %0;" : "+l"(acc) : "l"(a), "l"(b));
}
__device__ __forceinline__ float lo32(u64 v) { return __uint_as_float((unsigned)v); }
__device__ __forceinline__ float hi32(u64 v) { return __uint_as_float((unsigned)(v >> 32)); }

// ---------------------------------------------------------------------------
__device__ __forceinline__ void repack_one(const float* __restrict__ w, float* __restrict__ dst,
                                           int j, int CINR, int CINP, int COUT) {
    int co = j % COUT;
    int r = j / COUT;
    int ci = r % CINP;
    int t = r / CINP;
    dst[j] = (ci < CINR) ? w[(co * CINR + ci) * 27 + t] : 0.0f;
}

__global__ void k_init(const float* __restrict__ w0a, const float* __restrict__ w0b,
                       const float* __restrict__ wd0, const float* __restrict__ w1a,
                       const float* __restrict__ w1b) {
    int i = blockIdx.x * blockDim.x + threadIdx.x;
    if (i == 0) { g_n0 = 0; g_n1 = 0; }
    if (i < 1728) repack_one(w0a, g_WR0A, i, 3, 4, 16);
    else if (i < 8640) repack_one(w0b, g_WR0B, i - 1728, 16, 16, 16);
    else if (i < 22464) repack_one(wd0, g_WRD0, i - 8640, 16, 16, 32);
    else if (i < 50112) repack_one(w1a, g_WR1A, i - 22464, 32, 32, 32);
    else if (i < 77760) repack_one(w1b, g_WR1B, i - 50112, 32, 32, 32);
}

// ---------------------------------------------------------------------------
// Prep: masked input + ordered list0; m1 maxpool + ordered list1 + dense mask.
// Warp-aggregated appends: one atomicAdd per warp, lanes keep ascending order.
// NFULL/NHALF are multiples of 256 -> all branches warp-uniform.
// ---------------------------------------------------------------------------
__global__ void k_prep_all(const float* __restrict__ xf, const int* __restrict__ mask) {
    const int v = blockIdx.x * blockDim.x + threadIdx.x;
    const int lane = threadIdx.x & 31;

    if (v < NHALF) {
        int xx = v & 63, yy = (v >> 6) & 63, zz = v >> 12;
        int any = 0;
        for (int dz = 0; dz < 3; dz++) {
            int iz = 2 * zz - 1 + dz;
            if (iz < 0 || iz > 127) continue;
            for (int dy = 0; dy < 3; dy++) {
                int iy = 2 * yy - 1 + dy;
                if (iy < 0 || iy > 127) continue;
                for (int dx = 0; dx < 3; dx++) {
                    int ix = 2 * xx - 1 + dx;
                    if (ix < 0 || ix > 127) continue;
                    any |= mask[(iz * 128 + iy) * 128 + ix];
                }
            }
        }
        g_m1f[v] = any ? 1.0f : 0.0f;
        unsigned bal = __ballot_sync(0xffffffffu, any != 0);
        if (bal) {
            int ldr = __ffs(bal) - 1;
            int basep = 0;
            if (lane == ldr) basep = atomicAdd(&g_n1, __popc(bal));
            basep = __shfl_sync(0xffffffffu, basep, ldr);
            if (any) {
                int pre = __popc(bal & ((1u << lane) - 1));
                g_list1[basep + pre] = (unsigned)((zz << 12) | (yy << 6) | xx);
            }
        }
    }

    const int act = (v < NFULL) ? (mask[v] != 0) : 0;
    unsigned bal0 = __ballot_sync(0xffffffffu, act);
    if (act) {
        int xx = v & 127, yy = (v >> 7) & 127, zz = v >> 14;
        int vp = ((zz + 1) * L0 + (yy + 1)) * L0 + (xx + 1);
        float4 val;
        val.x = xf[v];
        val.y = xf[NFULL + v];
        val.z = xf[2 * NFULL + v];
        val.w = 0.0f;
        reinterpret_cast<float4*>(g_PX)[vp] = val;
    }
    if (bal0) {
        int ldr = __ffs(bal0) - 1;
        int basep = 0;
        if (lane == ldr) basep = atomicAdd(&g_n0, __popc(bal0));
        basep = __shfl_sync(0xffffffffu, basep, ldr);
        if (act) {
            int xx = v & 127, yy = (v >> 7) & 127, zz = v >> 14;
            int pre = __popc(bal0 & ((1u << lane) - 1));
            g_list0[basep + pre] = (unsigned)((zz << 14) | (yy << 7) | xx);
        }
    }
}

// ---------------------------------------------------------------------------
// Gather conv (stage 0 + downsample): unchanged math; benefits from ordered lists.
// ---------------------------------------------------------------------------
template <int CIN, int COUT, int VPT, int LIN, int S, int LOUT, int B>
__global__ void __launch_bounds__(256)
conv_gather(const float4* __restrict__ in4, float4* __restrict__ out4,
            const float4* __restrict__ wrep4,
            const float* __restrict__ scale, const float* __restrict__ shift,
            const unsigned* __restrict__ list, const int* __restrict__ pcount) {
    constexpr int C4 = CIN / 4;
    constexpr int O4 = COUT / 4;
    constexpr int WN4 = 27 * CIN * O4;

    extern __shared__ float4 smem4[];
    float4* w4s = smem4;
    float* s_sc = reinterpret_cast<float*>(smem4 + WN4);
    float* s_sh = s_sc + COUT;

    const int n = *pcount;
    const int base = blockIdx.x * (256 * VPT);
    if (base >= n) return;

    for (int i = threadIdx.x; i < WN4; i += 256) w4s[i] = wrep4[i];
    if (threadIdx.x < COUT) {
        s_sc[threadIdx.x] = scale[threadIdx.x];
        s_sh[threadIdx.x] = shift[threadIdx.x];
    }
    __syncthreads();

    int vin[VPT], vout[VPT];
    bool valid[VPT];
#pragma unroll
    for (int k = 0; k < VPT; k++) {
        int idx = base + k * 256 + (int)threadIdx.x;
        valid[k] = idx < n;
        unsigned p = list[valid[k] ? idx : base];
        int xx = (int)(p & ((1u << B) - 1));
        int yy = (int)((p >> B) & ((1u << B) - 1));
        int zz = (int)(p >> (2 * B));
        vin[k] = ((zz * S) * LIN + yy * S) * LIN + xx * S;
        vout[k] = ((zz + 1) * LOUT + (yy + 1)) * LOUT + (xx + 1);
    }

    u64 acc[VPT][COUT / 2];
#pragma unroll
    for (int k = 0; k < VPT; k++)
#pragma unroll
        for (int c = 0; c < COUT / 2; c++) acc[k][c] = 0ull;

#pragma unroll 1
    for (int dz = 0; dz < 3; dz++) {
#pragma unroll 1
        for (int dy = 0; dy < 3; dy++) {
#pragma unroll 1
            for (int dx = 0; dx < 3; dx++) {
                const int t = (dz * 3 + dy) * 3 + dx;
                const int off = (dz * LIN + dy) * LIN + dx;
                const float4* wt = w4s + t * (CIN * O4);
                const float4* pin[VPT];
#pragma unroll
                for (int k = 0; k < VPT; k++) pin[k] = in4 + (size_t)(vin[k] + off) * C4;
#pragma unroll
                for (int c4 = 0; c4 < C4; c4++) {
                    float4 iv[VPT];
#pragma unroll
                    for (int k = 0; k < VPT; k++) iv[k] = __ldg(pin[k] + c4);
#pragma unroll
                    for (int j = 0; j < 4; j++) {
                        const ulonglong2* wrow =
                            reinterpret_cast<const ulonglong2*>(wt + (c4 * 4 + j) * O4);
                        u64 aa[VPT];
#pragma unroll
                        for (int k = 0; k < VPT; k++) {
                            float a = (j == 0) ? iv[k].x : (j == 1) ? iv[k].y
                                                        : (j == 2) ? iv[k].z : iv[k].w;
                            aa[k] = pack2(a);
                        }
#pragma unroll
                        for (int o4 = 0; o4 < O4; o4++) {
                            ulonglong2 w = wrow[o4];
#pragma unroll
                            for (int k = 0; k < VPT; k++) {
                                fma2(acc[k][2 * o4 + 0], aa[k], w.x);
                                fma2(acc[k][2 * o4 + 1], aa[k], w.y);
                            }
                        }
                    }
                }
            }
        }
    }

#pragma unroll
    for (int k = 0; k < VPT; k++) {
        if (!valid[k]) continue;
        float4* po = out4 + (size_t)vout[k] * O4;
#pragma unroll
        for (int o4 = 0; o4 < O4; o4++) {
            u64 v0 = acc[k][2 * o4 + 0];
            u64 v1 = acc[k][2 * o4 + 1];
            float4 r;
            r.x = fmaxf(fmaf(lo32(v0), s_sc[4 * o4 + 0], s_sh[4 * o4 + 0]), 0.0f);
            r.y = fmaxf(fmaf(hi32(v0), s_sc[4 * o4 + 1], s_sh[4 * o4 + 1]), 0.0f);
            r.z = fmaxf(fmaf(lo32(v1), s_sc[4 * o4 + 2], s_sh[4 * o4 + 2]), 0.0f);
            r.w = fmaxf(fmaf(hi32(v1), s_sc[4 * o4 + 3], s_sh[4 * o4 + 3]), 0.0f);
            po[o4] = r;
        }
    }
}

// ---------------------------------------------------------------------------
// Dense tiled 32->32 conv, half res. Tile 8x8x8 (512 voxels), 256 threads,
// VPT=2 (z and z+4). Input processed in two 16-channel halves: halo 10^3
// voxels x 4 float4 with VS4=5 stride (conflict-free: lanes of a phase cover
// all 32 banks exactly once). Full 27-tap weights in smem; each weight
// LDS.128 now feeds 4 FMA2 (2 voxels x 2).
// ---------------------------------------------------------------------------
__global__ void __launch_bounds__(256)
conv_dense32(const float4* __restrict__ in4, float4* __restrict__ out4,
             const float4* __restrict__ wrep4,
             const float* __restrict__ scale, const float* __restrict__ shift,
             const float* __restrict__ m1f) {
    constexpr int HV = 10 * 10 * 10;
    constexpr int VS4 = 5;                   // float4 stride per halo voxel (4 used + 1 pad)
    constexpr int WN4 = 27 * 32 * 8;         // 6912 float4 weights

    extern __shared__ float4 smem4[];
    float4* s_w = smem4;                     // [tap][ci(32)][o4(8)]
    float4* s_in = smem4 + WN4;              // [hv][VS4] (current cin half)
    float* s_sc = reinterpret_cast<float*>(s_in + HV * VS4);
    float* s_sh = s_sc + 32;

    const int t = threadIdx.x;
    const int x0 = blockIdx.x * 8;
    const int y0 = blockIdx.y * 8;
    const int z0 = blockIdx.z * 8;

    for (int i = t; i < WN4; i += 256) s_w[i] = wrep4[i];
    if (t < 32) { s_sc[t] = scale[t]; s_sh[t] = shift[t]; }

    const int vx = t & 7;
    const int vy = (t >> 3) & 7;
    const int vz0 = t >> 6;                  // 0..3; voxels vz0 and vz0+4

    u64 acc[2][16];
#pragma unroll
    for (int k = 0; k < 2; k++)
#pragma unroll
        for (int c = 0; c < 16; c++) acc[k][c] = 0ull;

#pragma unroll 1
    for (int h = 0; h < 2; h++) {
        __syncthreads();                     // previous half fully consumed (and weights stored)
        for (int i = t; i < HV * 4; i += 256) {
            int hv = i >> 2, c4 = i & 3;
            int hx = hv % 10;
            int hy = (hv / 10) % 10;
            int hz = hv / 100;
            int g = ((z0 + hz) * L1 + (y0 + hy)) * L1 + (x0 + hx);
            s_in[hv * VS4 + c4] = in4[(size_t)g * 8 + h * 4 + c4];
        }
        __syncthreads();

#pragma unroll 1
        for (int dz = 0; dz < 3; dz++) {
#pragma unroll 1
            for (int dy = 0; dy < 3; dy++) {
#pragma unroll 1
                for (int dx = 0; dx < 3; dx++) {
                    const int tap = (dz * 3 + dy) * 3 + dx;
                    const float4* wt = s_w + tap * (32 * 8) + h * 16 * 8;
                    const int hv0 = ((vz0 + dz) * 10 + (vy + dy)) * 10 + (vx + dx);
                    const float4* pin0 = s_in + hv0 * VS4;
                    const float4* pin1 = s_in + (hv0 + 400) * VS4;  // vz0+4 -> +4*100 voxels
#pragma unroll
                    for (int c4 = 0; c4 < 4; c4++) {
                        float4 iv0 = pin0[c4];
                        float4 iv1 = pin1[c4];
#pragma unroll
                        for (int j = 0; j < 4; j++) {
                            u64 a0 = pack2((j == 0) ? iv0.x : (j == 1) ? iv0.y
                                                           : (j == 2) ? iv0.z : iv0.w);
                            u64 a1 = pack2((j == 0) ? iv1.x : (j == 1) ? iv1.y
                                                           : (j == 2) ? iv1.z : iv1.w);
                            const ulonglong2* wr =
                                reinterpret_cast<const ulonglong2*>(wt + (c4 * 4 + j) * 8);
#pragma unroll
                            for (int o4 = 0; o4 < 8; o4++) {
                                ulonglong2 w = wr[o4];
                                fma2(acc[0][2 * o4 + 0], a0, w.x);
                                fma2(acc[0][2 * o4 + 1], a0, w.y);
                                fma2(acc[1][2 * o4 + 0], a1, w.x);
                                fma2(acc[1][2 * o4 + 1], a1, w.y);
                            }
                        }
                    }
                }
            }
        }
    }

#pragma unroll
    for (int k = 0; k < 2; k++) {
        const int lz = z0 + vz0 + 4 * k, ly = y0 + vy, lx = x0 + vx;
        const float m = m1f[(lz * 64 + ly) * 64 + lx];
        float4* po = out4 + (size_t)(((lz + 1) * L1 + (ly + 1)) * L1 + (lx + 1)) * 8;
#pragma unroll
        for (int o4 = 0; o4 < 8; o4++) {
            u64 v0 = acc[k][2 * o4 + 0];
            u64 v1 = acc[k][2 * o4 + 1];
            float4 r;
            r.x = fmaxf(fmaf(lo32(v0), s_sc[4 * o4 + 0], s_sh[4 * o4 + 0]), 0.0f) * m;
            r.y = fmaxf(fmaf(hi32(v0), s_sc[4 * o4 + 1], s_sh[4 * o4 + 1]), 0.0f) * m;
            r.z = fmaxf(fmaf(lo32(v1), s_sc[4 * o4 + 2], s_sh[4 * o4 + 2]), 0.0f) * m;
            r.w = fmaxf(fmaf(hi32(v1), s_sc[4 * o4 + 3], s_sh[4 * o4 + 3]), 0.0f) * m;
            po[o4] = r;
        }
    }
}

// ---------------------------------------------------------------------------
__global__ void k_sample(const float4* __restrict__ Q, const float* __restrict__ coords,
                         float4* __restrict__ out, int npts) {
    int p = blockIdx.x * blockDim.x + threadIdx.x;
    if (p >= npts) return;
    float fx = (coords[3 * p + 0] + 1.0f) * 0.5f * 63.0f;
    float fy = (coords[3 * p + 1] + 1.0f) * 0.5f * 63.0f;
    float fz = (coords[3 * p + 2] + 1.0f) * 0.5f * 63.0f;
    int ix = (int)floorf(fx); ix = max(0, min(ix, 62));
    int iy = (int)floorf(fy); iy = max(0, min(iy, 62));
    int iz = (int)floorf(fz); iz = max(0, min(iz, 62));
    float tx = fx - (float)ix;
    float ty = fy - (float)iy;
    float tz = fz - (float)iz;

    float4 acc[8];
#pragma unroll
    for (int o = 0; o < 8; o++) acc[o] = make_float4(0.f, 0.f, 0.f, 0.f);

#pragma unroll
    for (int dz = 0; dz < 2; dz++) {
#pragma unroll
        for (int dy = 0; dy < 2; dy++) {
#pragma unroll
            for (int dx = 0; dx < 2; dx++) {
                float w = (dx ? tx : 1.0f - tx) * (dy ? ty : 1.0f - ty) * (dz ? tz : 1.0f - tz);
                int vp = ((iz + dz + 1) * L1 + (iy + dy + 1)) * L1 + (ix + dx + 1);
                const float4* q = Q + (size_t)vp * 8;
#pragma unroll
                for (int o = 0; o < 8; o++) {
                    float4 v = __ldg(q + o);
                    acc[o].x = fmaf(w, v.x, acc[o].x);
                    acc[o].y = fmaf(w, v.y, acc[o].y);
                    acc[o].z = fmaf(w, v.z, acc[o].z);
                    acc[o].w = fmaf(w, v.w, acc[o].w);
                }
            }
        }
    }
#pragma unroll
    for (int o = 0; o < 8; o++) out[(size_t)p * 8 + o] = acc[o];
}

// ---------------------------------------------------------------------------
extern "C" void kernel_launch(void* const* d_in, const int* in_sizes, int n_in,
                              void* d_out, int out_size) {
    const float* xf   = (const float*)d_in[0];
    const int* mask   = (const int*)d_in[1];
    const float* crd  = (const float*)d_in[2];
    const float* w0a  = (const float*)d_in[3];
    const float* s0a  = (const float*)d_in[4];
    const float* b0a  = (const float*)d_in[5];
    const float* w0b  = (const float*)d_in[6];
    const float* s0b  = (const float*)d_in[7];
    const float* b0b  = (const float*)d_in[8];
    const float* wd0  = (const float*)d_in[9];
    const float* sd0  = (const float*)d_in[10];
    const float* bd0  = (const float*)d_in[11];
    const float* w1a  = (const float*)d_in[12];
    const float* s1a  = (const float*)d_in[13];
    const float* b1a  = (const float*)d_in[14];
    const float* w1b  = (const float*)d_in[15];
    const float* s1b  = (const float*)d_in[16];
    const float* b1b  = (const float*)d_in[17];

    void *px, *p0, *p1, *q2, *q3, *q4, *l0, *l1, *pn0, *pn1, *m1f;
    void *wr0a, *wr0b, *wrd0, *wr1a, *wr1b;
    cudaGetSymbolAddress(&px, g_PX);
    cudaGetSymbolAddress(&p0, g_P0);
    cudaGetSymbolAddress(&p1, g_P1);
    cudaGetSymbolAddress(&q2, g_Q2);
    cudaGetSymbolAddress(&q3, g_Q3);
    cudaGetSymbolAddress(&q4, g_Q4);
    cudaGetSymbolAddress(&l0, g_list0);
    cudaGetSymbolAddress(&l1, g_list1);
    cudaGetSymbolAddress(&pn0, g_n0);
    cudaGetSymbolAddress(&pn1, g_n1);
    cudaGetSymbolAddress(&m1f, g_m1f);
    cudaGetSymbolAddress(&wr0a, g_WR0A);
    cudaGetSymbolAddress(&wr0b, g_WR0B);
    cudaGetSymbolAddress(&wrd0, g_WRD0);
    cudaGetSymbolAddress(&wr1a, g_WR1A);
    cudaGetSymbolAddress(&wr1b, g_WR1B);

    const int SM0A = (27 * 4 * 16 + 2 * 16) * 4;
    const int SM0B = (27 * 16 * 16 + 2 * 16) * 4;
    const int SMD0 = (27 * 16 * 32 + 2 * 32) * 4;
    const int SMD  = (27 * 32 * 8 + 1000 * 5) * 16 + 2 * 32 * 4;  // 190,848 + 256 B
    cudaFuncSetAttribute(conv_gather<16, 32, 2, L0, 2, L1, 6>,
                         cudaFuncAttributeMaxDynamicSharedMemorySize, SMD0);
    cudaFuncSetAttribute(conv_dense32,
                         cudaFuncAttributeMaxDynamicSharedMemorySize, SMD);

    int npts = in_sizes[2] / 3;

    k_init<<<(77760 + 255) / 256, 256>>>(w0a, w0b, wd0, w1a, w1b);
    k_prep_all<<<NFULL / 256, 256>>>(xf, mask);

    const int G0 = (NFULL + 511) / 512;
    conv_gather<4, 16, 2, L0, 1, L0, 7><<<G0, 256, SM0A>>>(
        (const float4*)px, (float4*)p0, (const float4*)wr0a, s0a, b0a,
        (const unsigned*)l0, (const int*)pn0);
    conv_gather<16, 16, 2, L0, 1, L0, 7><<<G0, 256, SM0B>>>(
        (const float4*)p0, (float4*)p1, (const float4*)wr0b, s0b, b0b,
        (const unsigned*)l0, (const int*)pn0);

    const int G1 = (NHALF + 511) / 512;
    conv_gather<16, 32, 2, L0, 2, L1, 6><<<G1, 256, SMD0>>>(
        (const float4*)p1, (float4*)q2, (const float4*)wrd0, sd0, bd0,
        (const unsigned*)l1, (const int*)pn1);

    dim3 gridD(8, 8, 8);
    conv_dense32<<<gridD, 256, SMD>>>(
        (const float4*)q2, (float4*)q3, (const float4*)wr1a, s1a, b1a, (const float*)m1f);
    conv_dense32<<<gridD, 256, SMD>>>(
        (const float4*)q3, (float4*)q4, (const float4*)wr1b, s1b, b1b, (const float*)m1f);

    k_sample<<<(npts + 255) / 256, 256>>>((const float4*)q4, crd, (float4*)d_out, npts);
}